// round 13
// baseline (speedup 1.0000x reference)
#include <cuda_runtime.h>
#include <cuda_bf16.h>
#include <math.h>
#include <stdint.h>

// ---------------- Problem constants ----------------
#define BATCH   4
#define HW      65536
#define CC      180
#define C1D     60
#define CAD     6
#define FF      720
#define HEADS   6
#define HD      30
#define NTOK    262144
#define NWIN    4096

// ---------------- Scratch ----------------
__device__ float g_qkv [(size_t)NTOK * 540];
__device__ float g_y   [NTOK * CC];
__device__ float g_xmid[NTOK * CC];
__device__ float g_poolp[1024 * CC];
__device__ float g_a   [BATCH * CC];

__device__ __nv_bfloat16 g_xnh[NTOK * CC],  g_xnl[NTOK * CC];
__device__ __nv_bfloat16 g_c1h[NTOK * C1D], g_c1l[NTOK * C1D];
__device__ __nv_bfloat16 g_atth[NTOK * CC], g_attl[NTOK * CC];
__device__ __nv_bfloat16 g_hh[(size_t)NTOK * FF], g_hl[(size_t)NTOK * FF];
__device__ __nv_bfloat16 g_wqh[540*CC],  g_wql[540*CC];
__device__ __nv_bfloat16 g_wph[CC*CC],   g_wpl[CC*CC];
__device__ __nv_bfloat16 g_wf1h[FF*CC],  g_wf1l[FF*CC];
__device__ __nv_bfloat16 g_wf2h[CC*FF],  g_wf2l[CC*FF];
__device__ __nv_bfloat16 g_w1th[9*C1D*CC], g_w1tl[9*C1D*CC];   // [tap][oc][ic]
__device__ __nv_bfloat16 g_w2th[9*CC*C1D], g_w2tl[9*CC*C1D];   // [tap][oc][ic]

__device__ __forceinline__ float gelu_f(float x) {
    return 0.5f * x * (1.0f + erff(x * 0.70710678118654752f));
}
__device__ __forceinline__ void split2(float f, __nv_bfloat16& h, __nv_bfloat16& l) {
    h = __float2bfloat16(f);
    l = __float2bfloat16(f - __bfloat162float(h));
}
__device__ __forceinline__ uint32_t smem_u32(const void* p) {
    uint32_t a;
    asm("{ .reg .u64 t; cvta.to.shared.u64 t, %1; cvt.u32.u64 %0, t; }" : "=r"(a) : "l"(p));
    return a;
}
__device__ __forceinline__ void ldsm_x4(uint32_t* r, uint32_t addr) {
    asm volatile("ldmatrix.sync.aligned.m8n8.x4.shared.b16 {%0,%1,%2,%3}, [%4];"
        : "=r"(r[0]), "=r"(r[1]), "=r"(r[2]), "=r"(r[3]) : "r"(addr));
}
__device__ __forceinline__ void mma16816(float* c, const uint32_t* a, const uint32_t* b) {
    asm volatile("mma.sync.aligned.m16n8k16.row.col.f32.bf16.bf16.f32 "
        "{%0,%1,%2,%3}, {%4,%5,%6,%7}, {%8,%9}, {%0,%1,%2,%3};"
        : "+f"(c[0]), "+f"(c[1]), "+f"(c[2]), "+f"(c[3])
        : "r"(a[0]), "r"(a[1]), "r"(a[2]), "r"(a[3]), "r"(b[0]), "r"(b[1]));
}
__device__ __forceinline__ void cp8(uint32_t saddr, const void* g, uint32_t bytes) {
    asm volatile("cp.async.ca.shared.global [%0], [%1], 8, %2;"
        :: "r"(saddr), "l"(g), "r"(bytes));
}
__device__ __forceinline__ void cp_commit() { asm volatile("cp.async.commit_group;"); }
template<int N> __device__ __forceinline__ void cp_wait() {
    asm volatile("cp.async.wait_group %0;" :: "n"(N));
}

// ---------------- weight split prep ----------------
__global__ void split_kernel(const float* __restrict__ src, __nv_bfloat16* __restrict__ hi,
                             __nv_bfloat16* __restrict__ lo, int n) {
    int i = blockIdx.x * 256 + threadIdx.x;
    if (i < n) { __nv_bfloat16 h, l; split2(src[i], h, l); hi[i] = h; lo[i] = l; }
}
__global__ void splitw_conv(const float* __restrict__ src, __nv_bfloat16* __restrict__ hi,
                            __nv_bfloat16* __restrict__ lo, int OC, int IC) {
    int i = blockIdx.x * 256 + threadIdx.x;
    int n = OC * IC * 9;
    if (i < n) {
        int tap = i % 9;
        int ic  = (i / 9) % IC;
        int oc  = i / (9 * IC);
        __nv_bfloat16 h, l; split2(src[i], h, l);
        size_t o = (size_t)tap * OC * IC + (size_t)oc * IC + ic;
        hi[o] = h; lo[o] = l;
    }
}

// ---------------- LayerNorm: bf16 hi/lo ----------------
__global__ void ln_kernel(const float* __restrict__ in, const float* __restrict__ g,
                          const float* __restrict__ bt,
                          __nv_bfloat16* __restrict__ oh, __nv_bfloat16* __restrict__ ol,
                          int ntok) {
    int gwarp = (blockIdx.x * blockDim.x + threadIdx.x) >> 5;
    int lane  = threadIdx.x & 31;
    if (gwarp >= ntok) return;
    const float* p = in + (size_t)gwarp * CC;
    float v[6]; float s = 0.f, s2 = 0.f;
#pragma unroll
    for (int k = 0; k < 6; k++) {
        int c = lane + 32 * k;
        float xv = (c < CC) ? p[c] : 0.f;
        v[k] = xv; s += xv; s2 += xv * xv;
    }
#pragma unroll
    for (int o = 16; o > 0; o >>= 1) {
        s  += __shfl_xor_sync(0xffffffffu, s,  o);
        s2 += __shfl_xor_sync(0xffffffffu, s2, o);
    }
    float mean = s * (1.f / CC);
    float var  = s2 * (1.f / CC) - mean * mean;
    float inv  = rsqrtf(var + 1e-5f);
    size_t base = (size_t)gwarp * CC;
#pragma unroll
    for (int k = 0; k < 6; k++) {
        int c = lane + 32 * k;
        if (c < CC) {
            float y = (v[k] - mean) * inv * g[c] + bt[c];
            __nv_bfloat16 h, l; split2(y, h, l);
            oh[base + c] = h; ol[base + c] = l;
        }
    }
}

// ================= A-resident GEMM (K = 180, padded to 192) =================
// smem: A hi [128x200] | A lo | B double-buffered (each: hi [64x200] | lo)
#define LDK   200
#define AR_L  25600             // 128*200
#define BR0   51200
#define BR_SZ 25600             // one B buffer (hi+lo)
#define BR_L  12800             // 64*200
#define SMEM_ARES ((BR0 + 2 * BR_SZ) * 2)   // 204800 B

// MODE 0: fp32 +bias | 1: gelu(+bias)->bf16 hi/lo | 2: proj epi
template<int MODE>
__global__ __launch_bounds__(256)
void gemm_ares(const __nv_bfloat16* __restrict__ Ah, const __nv_bfloat16* __restrict__ Al,
               const __nv_bfloat16* __restrict__ Bh, const __nv_bfloat16* __restrict__ Bl,
               const float* __restrict__ bias,
               const float* __restrict__ aux1, const float* __restrict__ aux2,
               const float* __restrict__ ga,
               float* __restrict__ outf, __nv_bfloat16* __restrict__ outh,
               __nv_bfloat16* __restrict__ outl, int N, int NT)
{
    extern __shared__ __nv_bfloat16 sm[];
    const uint32_t sbase = smem_u32(sm);
    const int tid  = threadIdx.x;
    const int warp = tid >> 5, lane = tid & 31;
    const int wm = warp >> 1, wn = warp & 1;
    const size_t m0 = (size_t)blockIdx.x * 128;

    const int aRow = (lane & 15), aColOff = (lane >> 4) << 3;
    const int bRow = ((lane >> 4) << 3) + (lane & 7), bColOff = ((lane >> 3) & 1) << 3;

    // ---- stage A (entire K) once ----
    for (int i = tid; i < 6144; i += 256) {
        int row = i / 48, c = i % 48;
        int k = c * 4;
        int vb = CC - k; vb = vb < 0 ? 0 : (vb > 4 ? 4 : vb);
        size_t off = (m0 + row) * (size_t)CC + (vb ? k : 0);
        uint32_t sa = sbase + (uint32_t)(row * LDK + k) * 2;
        cp8(sa,            Ah + off, (uint32_t)vb * 2);
        cp8(sa + AR_L * 2, Al + off, (uint32_t)vb * 2);
    }

#define B_STAGE(buf, nt) do { \
    for (int i = tid; i < 3072; i += 256) { \
        int row = i / 48, c = i % 48; \
        int k = c * 4; \
        int n_ = (nt) * 64 + row; \
        int vb = CC - k; vb = vb < 0 ? 0 : (vb > 4 ? 4 : vb); \
        if (n_ >= N) vb = 0; \
        size_t off = vb ? ((size_t)n_ * CC + k) : 0; \
        uint32_t sa = sbase + (uint32_t)(BR0 + (buf) * BR_SZ + row * LDK + k) * 2; \
        cp8(sa,            Bh + off, (uint32_t)vb * 2); \
        cp8(sa + BR_L * 2, Bl + off, (uint32_t)vb * 2); \
    } \
} while (0)

    B_STAGE(0, 0);
    cp_commit();

    for (int nt = 0; nt < NT; nt++) {
        const int cur = nt & 1;
        if (nt + 1 < NT) { B_STAGE(cur ^ 1, nt + 1); cp_commit(); cp_wait<1>(); }
        else cp_wait<0>();
        __syncthreads();

        float acc[2][4][4];
#pragma unroll
        for (int i = 0; i < 2; i++)
#pragma unroll
            for (int j = 0; j < 4; j++)
#pragma unroll
                for (int c = 0; c < 4; c++) acc[i][j][c] = 0.f;

        const uint32_t bbase = sbase + (uint32_t)(BR0 + cur * BR_SZ) * 2;
#pragma unroll
        for (int ks = 0; ks < 12; ks++) {
            const int kb = ks * 16;
            uint32_t aH[2][4], aL[2][4], bH[4][2], bL[4][2];
#pragma unroll
            for (int mi = 0; mi < 2; mi++) {
                int r = wm * 32 + mi * 16 + aRow;
                uint32_t adr = sbase + (uint32_t)(r * LDK + kb + aColOff) * 2;
                ldsm_x4(aH[mi], adr);
                ldsm_x4(aL[mi], adr + AR_L * 2);
            }
#pragma unroll
            for (int nf = 0; nf < 2; nf++) {
                int r = wn * 32 + nf * 16 + bRow;
                uint32_t adr = bbase + (uint32_t)(r * LDK + kb + bColOff) * 2;
                uint32_t t[4];
                ldsm_x4(t, adr);
                bH[nf*2][0] = t[0]; bH[nf*2][1] = t[1];
                bH[nf*2+1][0] = t[2]; bH[nf*2+1][1] = t[3];
                ldsm_x4(t, adr + BR_L * 2);
                bL[nf*2][0] = t[0]; bL[nf*2][1] = t[1];
                bL[nf*2+1][0] = t[2]; bL[nf*2+1][1] = t[3];
            }
#pragma unroll
            for (int mi = 0; mi < 2; mi++)
#pragma unroll
                for (int ni = 0; ni < 4; ni++) {
                    mma16816(acc[mi][ni], aH[mi], bH[ni]);
                    mma16816(acc[mi][ni], aH[mi], bL[ni]);
                    mma16816(acc[mi][ni], aL[mi], bH[ni]);
                }
        }

        // epilogue for this n-tile
        const int n0 = nt * 64;
#pragma unroll
        for (int mi = 0; mi < 2; mi++)
#pragma unroll
            for (int hh = 0; hh < 2; hh++) {
                size_t row = m0 + wm * 32 + mi * 16 + (lane >> 2) + hh * 8;
                int bb = (int)(row >> 16);
#pragma unroll
                for (int ni = 0; ni < 4; ni++) {
                    int n_ = n0 + wn * 32 + ni * 8 + (lane & 3) * 2;
                    if (n_ >= N) continue;
                    float v0 = acc[mi][ni][hh * 2 + 0] + bias[n_];
                    float v1 = acc[mi][ni][hh * 2 + 1] + bias[n_ + 1];
                    size_t o = row * (size_t)N + n_;
                    if (MODE == 0) {
                        *(float2*)(outf + o) = make_float2(v0, v1);
                    } else if (MODE == 1) {
                        float gg0 = gelu_f(v0), gg1 = gelu_f(v1);
                        __nv_bfloat16 h0, l0, h1, l1;
                        split2(gg0, h0, l0); split2(gg1, h1, l1);
                        __nv_bfloat162 hp; hp.x = h0; hp.y = h1;
                        __nv_bfloat162 lp; lp.x = l0; lp.y = l1;
                        *(__nv_bfloat162*)(outh + o) = hp;
                        *(__nv_bfloat162*)(outl + o) = lp;
                    } else {
                        float2 xv = *(const float2*)(aux1 + o);
                        float2 yv = *(const float2*)(aux2 + o);
                        *(float2*)(outf + o) = make_float2(
                            xv.x + v0 + yv.x * ga[bb * CC + n_],
                            xv.y + v1 + yv.y * ga[bb * CC + n_ + 1]);
                    }
                }
            }
        __syncthreads();
    }
#undef B_STAGE
}

// ---------------- tile geometry (double-buffered, chunked path) ----------------
#define LDT 72
#define E_AH 0
#define E_AL 9216
#define E_BH 18432
#define E_BL 23040
#define BUF_E 27648
#define SMEM_MMA (2 * BUF_E * 2)

// ---------------- chunked GEMM (kept for fc2, K=720) ----------------
// MODE 3: fc2 residual epilogue
template<int MODE>
__global__ __launch_bounds__(256)
void mma_gemm(const __nv_bfloat16* __restrict__ Ah, const __nv_bfloat16* __restrict__ Al,
              const __nv_bfloat16* __restrict__ Bh, const __nv_bfloat16* __restrict__ Bl,
              const float* __restrict__ bias,
              const float* __restrict__ aux1,
              float* __restrict__ outf, int N, int K)
{
    extern __shared__ __nv_bfloat16 sm[];
    const uint32_t sbase = smem_u32(sm);
    const int tid  = threadIdx.x;
    const int warp = tid >> 5, lane = tid & 31;
    const int wm = warp >> 1, wn = warp & 1;
    const size_t m0 = (size_t)blockIdx.y * 128;
    const int n0 = blockIdx.x * 64;

    float acc[2][4][4];
#pragma unroll
    for (int i = 0; i < 2; i++)
#pragma unroll
        for (int j = 0; j < 4; j++)
#pragma unroll
            for (int c = 0; c < 4; c++) acc[i][j][c] = 0.f;

    const int aRow = (lane & 15), aColOff = (lane >> 4) << 3;
    const int bRow = ((lane >> 4) << 3) + (lane & 7), bColOff = ((lane >> 3) & 1) << 3;
    const int nch = (K + 63) / 64;

#define G_STAGE(buf, kc) do { \
    const int kbase = (kc) * 64; \
    const uint32_t bb = sbase + (uint32_t)(buf) * (BUF_E * 2); \
    for (int i = tid; i < 2048; i += 256) { \
        int row = i >> 4, c = i & 15; \
        int k = kbase + c * 4; \
        int vb = K - k; vb = vb < 0 ? 0 : (vb > 4 ? 4 : vb); \
        size_t off = (m0 + row) * (size_t)K + (vb ? k : 0); \
        uint32_t sa = bb + (uint32_t)(row * LDT + c * 4) * 2; \
        cp8(sa,            Ah + off, (uint32_t)vb * 2); \
        cp8(sa + E_AL * 2, Al + off, (uint32_t)vb * 2); \
    } \
    for (int i = tid; i < 1024; i += 256) { \
        int row = i >> 4, c = i & 15; \
        int k = kbase + c * 4; \
        int vb = K - k; vb = vb < 0 ? 0 : (vb > 4 ? 4 : vb); \
        if (n0 + row >= N) vb = 0; \
        size_t off = (size_t)(n0 + (vb ? row : 0)) * K + (vb ? k : 0); \
        uint32_t sa = bb + (uint32_t)(E_BH + row * LDT + c * 4) * 2; \
        cp8(sa,                    Bh + off, (uint32_t)vb * 2); \
        cp8(sa + (E_BL - E_BH) * 2, Bl + off, (uint32_t)vb * 2); \
    } \
} while (0)

    G_STAGE(0, 0);
    cp_commit();
    for (int kc = 0; kc < nch; kc++) {
        const int cur = kc & 1;
        if (kc + 1 < nch) { G_STAGE(cur ^ 1, kc + 1); cp_commit(); cp_wait<1>(); }
        else cp_wait<0>();
        __syncthreads();

        __nv_bfloat16* bA = sm + cur * BUF_E;
#pragma unroll
        for (int ks = 0; ks < 4; ks++) {
            const int kb = ks * 16;
            uint32_t aH[2][4], aL[2][4], bH[4][2], bL[4][2];
#pragma unroll
            for (int mi = 0; mi < 2; mi++) {
                int r = wm * 32 + mi * 16 + aRow;
                uint32_t adr = smem_u32(bA + r * LDT + kb + aColOff);
                ldsm_x4(aH[mi], adr);
                ldsm_x4(aL[mi], adr + E_AL * 2);
            }
#pragma unroll
            for (int nf = 0; nf < 2; nf++) {
                int r = wn * 32 + nf * 16 + bRow;
                uint32_t adr = smem_u32(bA + E_BH + r * LDT + kb + bColOff);
                uint32_t t[4];
                ldsm_x4(t, adr);
                bH[nf*2][0] = t[0]; bH[nf*2][1] = t[1];
                bH[nf*2+1][0] = t[2]; bH[nf*2+1][1] = t[3];
                ldsm_x4(t, adr + (E_BL - E_BH) * 2);
                bL[nf*2][0] = t[0]; bL[nf*2][1] = t[1];
                bL[nf*2+1][0] = t[2]; bL[nf*2+1][1] = t[3];
            }
#pragma unroll
            for (int mi = 0; mi < 2; mi++)
#pragma unroll
                for (int ni = 0; ni < 4; ni++) {
                    mma16816(acc[mi][ni], aH[mi], bH[ni]);
                    mma16816(acc[mi][ni], aH[mi], bL[ni]);
                    mma16816(acc[mi][ni], aL[mi], bH[ni]);
                }
        }
        __syncthreads();
    }
#undef G_STAGE

#pragma unroll
    for (int mi = 0; mi < 2; mi++)
#pragma unroll
        for (int hh = 0; hh < 2; hh++) {
            size_t row = m0 + wm * 32 + mi * 16 + (lane >> 2) + hh * 8;
#pragma unroll
            for (int ni = 0; ni < 4; ni++) {
                int n_ = n0 + wn * 32 + ni * 8 + (lane & 3) * 2;
                if (n_ >= N) continue;
                float v0 = acc[mi][ni][hh * 2 + 0] + bias[n_];
                float v1 = acc[mi][ni][hh * 2 + 1] + bias[n_ + 1];
                size_t o = row * (size_t)N + n_;
                float2 xm = *(const float2*)(aux1 + o);
                *(float2*)(outf + o) = make_float2(xm.x + v0, xm.y + v1);
            }
        }
}

// ---------------- implicit-GEMM 3x3 conv, cp.async pipelined ----------------
template<int KSRC, int NCH, int OCT, int CMODE>
__global__ __launch_bounds__(256)
void conv_mma(const __nv_bfloat16* __restrict__ Ah, const __nv_bfloat16* __restrict__ Al,
              const __nv_bfloat16* __restrict__ Wh, const __nv_bfloat16* __restrict__ Wl,
              const float* __restrict__ bias,
              float* __restrict__ outf, __nv_bfloat16* __restrict__ outh,
              __nv_bfloat16* __restrict__ outl)
{
    extern __shared__ __nv_bfloat16 sm[];
    const uint32_t sbase = smem_u32(sm);
    const int tid  = threadIdx.x;
    const int warp = tid >> 5, lane = tid & 31;
    const int wm = warp >> 1, wn = warp & 1;
    const size_t m0 = (size_t)blockIdx.y * 128;
    const int oc0 = blockIdx.x * 60;

    float acc[2][4][4];
#pragma unroll
    for (int i = 0; i < 2; i++)
#pragma unroll
        for (int j = 0; j < 4; j++)
#pragma unroll
            for (int c = 0; c < 4; c++) acc[i][j][c] = 0.f;

    const int aRow = (lane & 15), aColOff = (lane >> 4) << 3;
    const int bRow = ((lane >> 4) << 3) + (lane & 7), bColOff = ((lane >> 3) & 1) << 3;
    const int NIT = 9 * NCH;

#define C_STAGE(buf, it) do { \
    const int tap = (it) / NCH; \
    const int kbase = ((it) % NCH) * 64; \
    const int dr = tap / 3 - 1, dc = tap % 3 - 1; \
    const int toff = dr * 256 + dc; \
    const uint32_t bb = sbase + (uint32_t)(buf) * (BUF_E * 2); \
    for (int i = tid; i < 2048; i += 256) { \
        int row = i >> 4, c = i & 15; \
        int t = (int)(m0 + row); \
        int hh2 = (t >> 8) & 255, ww2 = t & 255; \
        int k = kbase + c * 4; \
        int vb = KSRC - k; vb = vb < 0 ? 0 : (vb > 4 ? 4 : vb); \
        if ((unsigned)(hh2 + dr) >= 256u || (unsigned)(ww2 + dc) >= 256u) vb = 0; \
        size_t off = vb ? ((size_t)(t + toff) * KSRC + k) : 0; \
        uint32_t sa = bb + (uint32_t)(row * LDT + c * 4) * 2; \
        cp8(sa,            Ah + off, (uint32_t)vb * 2); \
        cp8(sa + E_AL * 2, Al + off, (uint32_t)vb * 2); \
    } \
    for (int i = tid; i < 1024; i += 256) { \
        int n = i >> 4, c = i & 15; \
        int k = kbase + c * 4; \
        int vb = KSRC - k; vb = vb < 0 ? 0 : (vb > 4 ? 4 : vb); \
        if (n >= 60) vb = 0; \
        size_t off = vb ? ((size_t)tap * OCT * KSRC + (size_t)(oc0 + n) * KSRC + k) : 0; \
        uint32_t sa = bb + (uint32_t)(E_BH + n * LDT + c * 4) * 2; \
        cp8(sa,                     Wh + off, (uint32_t)vb * 2); \
        cp8(sa + (E_BL - E_BH) * 2, Wl + off, (uint32_t)vb * 2); \
    } \
} while (0)

    C_STAGE(0, 0);
    cp_commit();
    for (int it = 0; it < NIT; it++) {
        const int cur = it & 1;
        if (it + 1 < NIT) { C_STAGE(cur ^ 1, it + 1); cp_commit(); cp_wait<1>(); }
        else cp_wait<0>();
        __syncthreads();

        __nv_bfloat16* bA = sm + cur * BUF_E;
#pragma unroll
        for (int ks = 0; ks < 4; ks++) {
            const int kbb = ks * 16;
            uint32_t aH[2][4], aL[2][4], bH[4][2], bL[4][2];
#pragma unroll
            for (int mi = 0; mi < 2; mi++) {
                int r = wm * 32 + mi * 16 + aRow;
                uint32_t adr = smem_u32(bA + r * LDT + kbb + aColOff);
                ldsm_x4(aH[mi], adr);
                ldsm_x4(aL[mi], adr + E_AL * 2);
            }
#pragma unroll
            for (int nf = 0; nf < 2; nf++) {
                int r = wn * 32 + nf * 16 + bRow;
                uint32_t adr = smem_u32(bA + E_BH + r * LDT + kbb + bColOff);
                uint32_t t4[4];
                ldsm_x4(t4, adr);
                bH[nf*2][0] = t4[0]; bH[nf*2][1] = t4[1];
                bH[nf*2+1][0] = t4[2]; bH[nf*2+1][1] = t4[3];
                ldsm_x4(t4, adr + (E_BL - E_BH) * 2);
                bL[nf*2][0] = t4[0]; bL[nf*2][1] = t4[1];
                bL[nf*2+1][0] = t4[2]; bL[nf*2+1][1] = t4[3];
            }
#pragma unroll
            for (int mi = 0; mi < 2; mi++)
#pragma unroll
                for (int ni = 0; ni < 4; ni++) {
                    mma16816(acc[mi][ni], aH[mi], bH[ni]);
                    mma16816(acc[mi][ni], aH[mi], bL[ni]);
                    mma16816(acc[mi][ni], aL[mi], bH[ni]);
                }
        }
        __syncthreads();
    }
#undef C_STAGE

#pragma unroll
    for (int mi = 0; mi < 2; mi++)
#pragma unroll
        for (int hh = 0; hh < 2; hh++) {
            size_t row = m0 + wm * 32 + mi * 16 + (lane >> 2) + hh * 8;
#pragma unroll
            for (int ni = 0; ni < 4; ni++) {
                int n_ = wn * 32 + ni * 8 + (lane & 3) * 2;
                if (n_ >= 60) continue;
                int oc = oc0 + n_;
                float v0 = acc[mi][ni][hh * 2 + 0] + bias[oc];
                float v1 = acc[mi][ni][hh * 2 + 1] + bias[oc + 1];
                size_t o = row * (size_t)OCT + oc;
                if (CMODE == 0) {
                    float gg0 = gelu_f(v0), gg1 = gelu_f(v1);
                    __nv_bfloat16 h0, l0, h1, l1;
                    split2(gg0, h0, l0); split2(gg1, h1, l1);
                    __nv_bfloat162 hp; hp.x = h0; hp.y = h1;
                    __nv_bfloat162 lp; lp.x = l0; lp.y = l1;
                    *(__nv_bfloat162*)(outh + o) = hp;
                    *(__nv_bfloat162*)(outl + o) = lp;
                } else {
                    *(float2*)(outf + o) = make_float2(v0, v1);
                }
            }
        }
}

// ---------------- channel pooling (stage 1) ----------------
__global__ __launch_bounds__(256)
void pool_partial_kernel(const float* __restrict__ y, float* __restrict__ pp) {
    __shared__ float s[64 * CC];
    int tid = threadIdx.x;
    int blk = blockIdx.x;
    size_t base = (size_t)blk * 256 * CC;
    float acc = 0.f;
    for (int it = 0; it < 4; it++) {
        __syncthreads();
        const float4* src = (const float4*)(y + base + (size_t)it * 64 * CC);
        float4* d4 = (float4*)s;
        for (int i = tid; i < 64 * CC / 4; i += 256) d4[i] = src[i];
        __syncthreads();
        if (tid < CC) {
#pragma unroll
            for (int t = 0; t < 64; t++) acc += s[t * CC + tid];
        }
    }
    if (tid < CC) pp[blk * CC + tid] = acc;
}

// ---------------- channel attention ----------------
__global__ void ca_kernel(const float* __restrict__ poolp,
                          const float* __restrict__ w1, const float* __restrict__ b1,
                          const float* __restrict__ w2, const float* __restrict__ b2,
                          float* __restrict__ ga) {
    int b = blockIdx.x;
    int t = threadIdx.x;
    __shared__ float mean[CC];
    __shared__ float sq[CAD];
    if (t < CC) {
        float a = 0.f;
        for (int k = 0; k < 256; k++) a += poolp[(size_t)(b * 256 + k) * CC + t];
        mean[t] = a * (1.f / 65536.f);
    }
    __syncthreads();
    if (t < CAD) {
        float a = b1[t];
        for (int c = 0; c < CC; c++) a += mean[c] * w1[t * CC + c];
        sq[t] = fmaxf(a, 0.f);
    }
    __syncthreads();
    if (t < CC) {
        float a = b2[t];
#pragma unroll
        for (int j = 0; j < CAD; j++) a += sq[j] * w2[t * CAD + j];
        ga[b * CC + t] = 0.01f / (1.f + expf(-a));
    }
}

// ---------------- window attention ----------------
__global__ __launch_bounds__(256)
void attn_kernel(const float* __restrict__ qkv, const float* __restrict__ bias_table,
                 const int* __restrict__ rpi,
                 __nv_bfloat16* __restrict__ atth, __nv_bfloat16* __restrict__ attl) {
    extern __shared__ float smf[];
    float* sQ = smf;
    float* sK = sQ + 64 * 33;
    float* sV = sK + 64 * 33;
    float* sA = sV + 64 * 33;
    int*   sR = (int*)(sA + 64 * 66);

    const int tid = threadIdx.x;
    const int b   = blockIdx.x >> 10;
    const int win = blockIdx.x & 1023;
    const int wr  = win >> 5, wc = win & 31;
    const int row0 = b * HW + (wr * 8) * 256 + wc * 8;

    for (int idx = tid; idx < 4096; idx += 256) sR[idx] = rpi[idx];

    const float scale = 0.18257418583505536f;
    for (int h = 0; h < HEADS; h++) {
        __syncthreads();
        for (int idx = tid; idx < 1920; idx += 256) {
            int i = idx / 30, d = idx % 30;
            int gt = row0 + (i >> 3) * 256 + (i & 7);
            const float* p = qkv + (size_t)gt * 540 + h * HD + d;
            sQ[i * 33 + d] = p[0] * scale;
            sK[i * 33 + d] = p[180];
            sV[i * 33 + d] = p[360];
        }
        __syncthreads();
        for (int idx = tid; idx < 2048; idx += 256) {
            int j = idx & 63, ip = idx >> 6;
            int i0 = ip * 2, i1 = i0 + 1;
            float s0 = bias_table[sR[i0 * 64 + j] * HEADS + h];
            float s1 = bias_table[sR[i1 * 64 + j] * HEADS + h];
            const float* q0 = sQ + i0 * 33;
            const float* q1 = sQ + i1 * 33;
            const float* kp = sK + j * 33;
#pragma unroll
            for (int d = 0; d < HD; d++) {
                float kv = kp[d];
                s0 += q0[d] * kv; s1 += q1[d] * kv;
            }
            sA[i0 * 66 + j] = s0; sA[i1 * 66 + j] = s1;
        }
        __syncthreads();
        {
            int w = tid >> 5, lane = tid & 31;
            for (int rrow = w; rrow < 64; rrow += 8) {
                float* row = sA + rrow * 66;
                float v0 = row[lane], v1 = row[lane + 32];
                float m = fmaxf(v0, v1);
#pragma unroll
                for (int o = 16; o > 0; o >>= 1) m = fmaxf(m, __shfl_xor_sync(0xffffffffu, m, o));
                float e0 = expf(v0 - m), e1 = expf(v1 - m);
                float s = e0 + e1;
#pragma unroll
                for (int o = 16; o > 0; o >>= 1) s += __shfl_xor_sync(0xffffffffu, s, o);
                float inv = 1.f / s;
                row[lane] = e0 * inv; row[lane + 32] = e1 * inv;
            }
        }
        __syncthreads();
        for (int idx = tid; idx < 960; idx += 256) {
            int d = idx % 30, ip = idx / 30;
            int i0 = ip * 2, i1 = i0 + 1;
            const float* a0 = sA + i0 * 66;
            const float* a1 = sA + i1 * 66;
            float o0 = 0.f, o1 = 0.f;
#pragma unroll 8
            for (int j = 0; j < 64; j++) {
                float vv = sV[j * 33 + d];
                o0 += a0[j] * vv; o1 += a1[j] * vv;
            }
            int gt0 = row0 + (i0 >> 3) * 256 + (i0 & 7);
            int gt1 = row0 + (i1 >> 3) * 256 + (i1 & 7);
            size_t p0 = (size_t)gt0 * CC + h * HD + d;
            size_t p1 = (size_t)gt1 * CC + h * HD + d;
            __nv_bfloat16 hh, ll;
            split2(o0, hh, ll); atth[p0] = hh; attl[p0] = ll;
            split2(o1, hh, ll); atth[p1] = hh; attl[p1] = ll;
        }
    }
}

// ---------------- host launch ----------------
extern "C" void kernel_launch(void* const* d_in, const int* in_sizes, int n_in,
                              void* d_out, int out_size) {
    const float* x          = (const float*)d_in[0];
    const float* ln1_g      = (const float*)d_in[1];
    const float* ln1_b      = (const float*)d_in[2];
    const float* qkv_w      = (const float*)d_in[3];
    const float* qkv_b      = (const float*)d_in[4];
    const float* bias_table = (const float*)d_in[5];
    const float* proj_w     = (const float*)d_in[6];
    const float* proj_b     = (const float*)d_in[7];
    const float* cab_w1     = (const float*)d_in[8];
    const float* cab_b1     = (const float*)d_in[9];
    const float* cab_w2     = (const float*)d_in[10];
    const float* cab_b2     = (const float*)d_in[11];
    const float* ca_w1      = (const float*)d_in[12];
    const float* ca_b1      = (const float*)d_in[13];
    const float* ca_w2      = (const float*)d_in[14];
    const float* ca_b2      = (const float*)d_in[15];
    const float* ln2_g      = (const float*)d_in[16];
    const float* ln2_b      = (const float*)d_in[17];
    const float* fc1_w      = (const float*)d_in[18];
    const float* fc1_b      = (const float*)d_in[19];
    const float* fc2_w      = (const float*)d_in[20];
    const float* fc2_b      = (const float*)d_in[21];
    const int*   rpi        = (const int*)d_in[22];
    float* out = (float*)d_out;

    float *p_qkv, *p_y, *p_xmid, *p_poolp, *p_a;
    __nv_bfloat16 *p_xnh, *p_xnl, *p_c1h, *p_c1l, *p_atth, *p_attl, *p_hh, *p_hl;
    __nv_bfloat16 *p_wqh, *p_wql, *p_wph, *p_wpl, *p_wf1h, *p_wf1l, *p_wf2h, *p_wf2l;
    __nv_bfloat16 *p_w1th, *p_w1tl, *p_w2th, *p_w2tl;
    cudaGetSymbolAddress((void**)&p_qkv,   g_qkv);
    cudaGetSymbolAddress((void**)&p_y,     g_y);
    cudaGetSymbolAddress((void**)&p_xmid,  g_xmid);
    cudaGetSymbolAddress((void**)&p_poolp, g_poolp);
    cudaGetSymbolAddress((void**)&p_a,     g_a);
    cudaGetSymbolAddress((void**)&p_xnh,   g_xnh);
    cudaGetSymbolAddress((void**)&p_xnl,   g_xnl);
    cudaGetSymbolAddress((void**)&p_c1h,   g_c1h);
    cudaGetSymbolAddress((void**)&p_c1l,   g_c1l);
    cudaGetSymbolAddress((void**)&p_atth,  g_atth);
    cudaGetSymbolAddress((void**)&p_attl,  g_attl);
    cudaGetSymbolAddress((void**)&p_hh,    g_hh);
    cudaGetSymbolAddress((void**)&p_hl,    g_hl);
    cudaGetSymbolAddress((void**)&p_wqh,   g_wqh);
    cudaGetSymbolAddress((void**)&p_wql,   g_wql);
    cudaGetSymbolAddress((void**)&p_wph,   g_wph);
    cudaGetSymbolAddress((void**)&p_wpl,   g_wpl);
    cudaGetSymbolAddress((void**)&p_wf1h,  g_wf1h);
    cudaGetSymbolAddress((void**)&p_wf1l,  g_wf1l);
    cudaGetSymbolAddress((void**)&p_wf2h,  g_wf2h);
    cudaGetSymbolAddress((void**)&p_wf2l,  g_wf2l);
    cudaGetSymbolAddress((void**)&p_w1th,  g_w1th);
    cudaGetSymbolAddress((void**)&p_w1tl,  g_w1tl);
    cudaGetSymbolAddress((void**)&p_w2th,  g_w2th);
    cudaGetSymbolAddress((void**)&p_w2tl,  g_w2tl);

    const int smem_attn = (3 * 64 * 33 + 64 * 66) * 4 + 4096 * 4;

    cudaFuncSetAttribute(attn_kernel,  cudaFuncAttributeMaxDynamicSharedMemorySize, smem_attn);
    cudaFuncSetAttribute(mma_gemm<3>, cudaFuncAttributeMaxDynamicSharedMemorySize, SMEM_MMA);
    cudaFuncSetAttribute(gemm_ares<0>, cudaFuncAttributeMaxDynamicSharedMemorySize, SMEM_ARES);
    cudaFuncSetAttribute(gemm_ares<1>, cudaFuncAttributeMaxDynamicSharedMemorySize, SMEM_ARES);
    cudaFuncSetAttribute(gemm_ares<2>, cudaFuncAttributeMaxDynamicSharedMemorySize, SMEM_ARES);
    cudaFuncSetAttribute((conv_mma<CC, 3, C1D, 0>), cudaFuncAttributeMaxDynamicSharedMemorySize, SMEM_MMA);
    cudaFuncSetAttribute((conv_mma<C1D, 1, CC, 1>), cudaFuncAttributeMaxDynamicSharedMemorySize, SMEM_MMA);

    // 0. weight splits
    split_kernel<<<(540*CC + 255) / 256, 256>>>(qkv_w, p_wqh, p_wql, 540*CC);
    split_kernel<<<(CC*CC  + 255) / 256, 256>>>(proj_w, p_wph, p_wpl, CC*CC);
    split_kernel<<<(FF*CC  + 255) / 256, 256>>>(fc1_w, p_wf1h, p_wf1l, FF*CC);
    split_kernel<<<(CC*FF  + 255) / 256, 256>>>(fc2_w, p_wf2h, p_wf2l, CC*FF);
    splitw_conv<<<(9*C1D*CC + 255) / 256, 256>>>(cab_w1, p_w1th, p_w1tl, C1D, CC);
    splitw_conv<<<(9*CC*C1D + 255) / 256, 256>>>(cab_w2, p_w2th, p_w2tl, CC, C1D);

    // 1. LN1
    ln_kernel<<<NTOK / 8, 256>>>(x, ln1_g, ln1_b, p_xnh, p_xnl, NTOK);
    // 2. conv branch
    conv_mma<CC, 3, C1D, 0><<<dim3(1, 2048), 256, SMEM_MMA>>>(
        p_xnh, p_xnl, p_w1th, p_w1tl, cab_b1, nullptr, p_c1h, p_c1l);
    conv_mma<C1D, 1, CC, 1><<<dim3(3, 2048), 256, SMEM_MMA>>>(
        p_c1h, p_c1l, p_w2th, p_w2tl, cab_b2, p_y, nullptr, nullptr);
    pool_partial_kernel<<<1024, 256>>>(p_y, p_poolp);
    ca_kernel<<<BATCH, 192>>>(p_poolp, ca_w1, ca_b1, ca_w2, ca_b2, p_a);
    // 3. QKV GEMM (A-resident) + window attention
    gemm_ares<0><<<2048, 256, SMEM_ARES>>>(p_xnh, p_xnl, p_wqh, p_wql, qkv_b,
                                           nullptr, nullptr, nullptr,
                                           p_qkv, nullptr, nullptr, 540, 9);
    attn_kernel<<<NWIN, 256, smem_attn>>>(p_qkv, bias_table, rpi, p_atth, p_attl);
    // 4. proj + residual + conv add (A-resident)
    gemm_ares<2><<<2048, 256, SMEM_ARES>>>(p_atth, p_attl, p_wph, p_wpl, proj_b,
                                           x, p_y, p_a,
                                           p_xmid, nullptr, nullptr, CC, 3);
    // 5. MLP
    ln_kernel<<<NTOK / 8, 256>>>(p_xmid, ln2_g, ln2_b, p_xnh, p_xnl, NTOK);
    gemm_ares<1><<<2048, 256, SMEM_ARES>>>(p_xnh, p_xnl, p_wf1h, p_wf1l, fc1_b,
                                           nullptr, nullptr, nullptr,
                                           nullptr, p_hh, p_hl, FF, 12);
    mma_gemm<3><<<dim3(3, 2048), 256, SMEM_MMA>>>(p_hh, p_hl, p_wf2h, p_wf2l, fc2_b,
                                                  p_xmid, out, CC, FF);
}

// round 14
// speedup vs baseline: 1.4179x; 1.4179x over previous
#include <cuda_runtime.h>
#include <cuda_fp16.h>
#include <math.h>
#include <stdint.h>

// ---------------- Problem constants ----------------
#define BATCH   4
#define HW      65536
#define CC      180
#define C1D     60
#define CAD     6
#define FF      720
#define HEADS   6
#define HD      30
#define NTOK    262144
#define NWIN    4096

// ---------------- Scratch ----------------
__device__ float g_qkv [(size_t)NTOK * 540];
__device__ float g_y   [NTOK * CC];
__device__ float g_xmid[NTOK * CC];
__device__ float g_poolp[1024 * CC];
__device__ float g_a   [BATCH * CC];

__device__ __half g_xnh[NTOK * CC],  g_xnl[NTOK * CC];
__device__ __half g_c1h[NTOK * C1D];
__device__ __half g_atth[NTOK * CC], g_attl[NTOK * CC];
__device__ __half g_hh[(size_t)NTOK * FF], g_hl[(size_t)NTOK * FF];
__device__ __half g_wqh[540*CC];
__device__ __half g_wph[CC*CC];
__device__ __half g_wf1h[FF*CC];
__device__ __half g_wf2h[CC*FF];
__device__ __half g_w1th[9*C1D*CC];   // [tap][oc][ic]
__device__ __half g_w2th[9*CC*C1D];   // [tap][oc][ic]

__device__ __forceinline__ float gelu_f(float x) {
    return 0.5f * x * (1.0f + erff(x * 0.70710678118654752f));
}
__device__ __forceinline__ void split2h(float f, __half& h, __half& l) {
    h = __float2half_rn(f);
    l = __float2half_rn(f - __half2float(h));
}
__device__ __forceinline__ uint32_t smem_u32(const void* p) {
    uint32_t a;
    asm("{ .reg .u64 t; cvta.to.shared.u64 t, %1; cvt.u32.u64 %0, t; }" : "=r"(a) : "l"(p));
    return a;
}
__device__ __forceinline__ void ldsm_x4(uint32_t* r, uint32_t addr) {
    asm volatile("ldmatrix.sync.aligned.m8n8.x4.shared.b16 {%0,%1,%2,%3}, [%4];"
        : "=r"(r[0]), "=r"(r[1]), "=r"(r[2]), "=r"(r[3]) : "r"(addr));
}
__device__ __forceinline__ void mma16816(float* c, const uint32_t* a, const uint32_t* b) {
    asm volatile("mma.sync.aligned.m16n8k16.row.col.f32.f16.f16.f32 "
        "{%0,%1,%2,%3}, {%4,%5,%6,%7}, {%8,%9}, {%0,%1,%2,%3};"
        : "+f"(c[0]), "+f"(c[1]), "+f"(c[2]), "+f"(c[3])
        : "r"(a[0]), "r"(a[1]), "r"(a[2]), "r"(a[3]), "r"(b[0]), "r"(b[1]));
}
__device__ __forceinline__ void cp8(uint32_t saddr, const void* g, uint32_t bytes) {
    asm volatile("cp.async.ca.shared.global [%0], [%1], 8, %2;"
        :: "r"(saddr), "l"(g), "r"(bytes));
}
__device__ __forceinline__ void cp_commit() { asm volatile("cp.async.commit_group;"); }
template<int N> __device__ __forceinline__ void cp_wait() {
    asm volatile("cp.async.wait_group %0;" :: "n"(N));
}

// ---------------- fused weight prep (fp32 -> fp16, conv transposed) ----------------
#define NWQ  (540*CC)
#define NWP  (CC*CC)
#define NWF1 (FF*CC)
#define NWF2 (CC*FF)
#define NW1  (9*C1D*CC)
#define NW2  (9*CC*C1D)
__global__ void prep_weights(const float* __restrict__ wq, const float* __restrict__ wp,
                             const float* __restrict__ wf1, const float* __restrict__ wf2,
                             const float* __restrict__ cw1, const float* __restrict__ cw2,
                             __half* __restrict__ dq, __half* __restrict__ dp,
                             __half* __restrict__ df1, __half* __restrict__ df2,
                             __half* __restrict__ d1t, __half* __restrict__ d2t) {
    int i = blockIdx.x * 256 + threadIdx.x;
    if (i < NWQ) { dq[i] = __float2half_rn(wq[i]); return; }
    i -= NWQ;
    if (i < NWP) { dp[i] = __float2half_rn(wp[i]); return; }
    i -= NWP;
    if (i < NWF1) { df1[i] = __float2half_rn(wf1[i]); return; }
    i -= NWF1;
    if (i < NWF2) { df2[i] = __float2half_rn(wf2[i]); return; }
    i -= NWF2;
    if (i < NW1) {
        int tap = i % 9, ic = (i / 9) % CC, oc = i / (9 * CC);
        d1t[(size_t)tap * C1D * CC + (size_t)oc * CC + ic] = __float2half_rn(cw1[i]);
        return;
    }
    i -= NW1;
    if (i < NW2) {
        int tap = i % 9, ic = (i / 9) % C1D, oc = i / (9 * C1D);
        d2t[(size_t)tap * CC * C1D + (size_t)oc * C1D + ic] = __float2half_rn(cw2[i]);
    }
}
#define NPREP (NWQ + NWP + NWF1 + NWF2 + NW1 + NW2)

// ---------------- LayerNorm: fp16 hi/lo ----------------
__global__ void ln_kernel(const float* __restrict__ in, const float* __restrict__ g,
                          const float* __restrict__ bt,
                          __half* __restrict__ oh, __half* __restrict__ ol,
                          int ntok) {
    int gwarp = (blockIdx.x * blockDim.x + threadIdx.x) >> 5;
    int lane  = threadIdx.x & 31;
    if (gwarp >= ntok) return;
    const float* p = in + (size_t)gwarp * CC;
    float v[6]; float s = 0.f, s2 = 0.f;
#pragma unroll
    for (int k = 0; k < 6; k++) {
        int c = lane + 32 * k;
        float xv = (c < CC) ? p[c] : 0.f;
        v[k] = xv; s += xv; s2 += xv * xv;
    }
#pragma unroll
    for (int o = 16; o > 0; o >>= 1) {
        s  += __shfl_xor_sync(0xffffffffu, s,  o);
        s2 += __shfl_xor_sync(0xffffffffu, s2, o);
    }
    float mean = s * (1.f / CC);
    float var  = s2 * (1.f / CC) - mean * mean;
    float inv  = rsqrtf(var + 1e-5f);
    size_t base = (size_t)gwarp * CC;
#pragma unroll
    for (int k = 0; k < 6; k++) {
        int c = lane + 32 * k;
        if (c < CC) {
            float y = (v[k] - mean) * inv * g[c] + bt[c];
            __half h, l; split2h(y, h, l);
            oh[base + c] = h; ol[base + c] = l;
        }
    }
}

// ---------------- tile geometry ----------------
#define LDT 72
// GEMM buffers: A hi [128x72] | A lo | B hi [64x72]
#define E_AL 9216
#define E_BH 18432
#define BUF_E 23040
#define SMEM_MMA (2 * BUF_E * 2)    // 92160 B
// conv buffers: A hi [128x72] | W hi [64x72]
#define CE_B 9216
#define CBUF 13824
#define SMEM_CONV (2 * CBUF * 2)    // 55296 B

// ---------------- fp16 mma.sync GEMM, 2-pass (A hi/lo, B hi) ----------------
// MODE 0: fp32 +bias | 1: gelu(+bias)->fp16 hi/lo | 2: proj epi | 3: fc2 epi
template<int MODE>
__global__ __launch_bounds__(256)
void mma_gemm(const __half* __restrict__ Ah, const __half* __restrict__ Al,
              const __half* __restrict__ Bh,
              const float* __restrict__ bias,
              const float* __restrict__ aux1, const float* __restrict__ aux2,
              const float* __restrict__ ga,
              float* __restrict__ outf, __half* __restrict__ outh,
              __half* __restrict__ outl, int N, int K)
{
    extern __shared__ __half sm[];
    const uint32_t sbase = smem_u32(sm);
    const int tid  = threadIdx.x;
    const int warp = tid >> 5, lane = tid & 31;
    const int wm = warp >> 1, wn = warp & 1;
    const size_t m0 = (size_t)blockIdx.y * 128;
    const int n0 = blockIdx.x * 64;

    float acc[2][4][4];
#pragma unroll
    for (int i = 0; i < 2; i++)
#pragma unroll
        for (int j = 0; j < 4; j++)
#pragma unroll
            for (int c = 0; c < 4; c++) acc[i][j][c] = 0.f;

    const int aRow = (lane & 15), aColOff = (lane >> 4) << 3;
    const int bRow = ((lane >> 4) << 3) + (lane & 7), bColOff = ((lane >> 3) & 1) << 3;
    const int nch = (K + 63) / 64;

#define G_STAGE(buf, kc) do { \
    const int kbase = (kc) * 64; \
    const uint32_t bb = sbase + (uint32_t)(buf) * (BUF_E * 2); \
    for (int i = tid; i < 2048; i += 256) { \
        int row = i >> 4, c = i & 15; \
        int k = kbase + c * 4; \
        int vb = K - k; vb = vb < 0 ? 0 : (vb > 4 ? 4 : vb); \
        size_t off = (m0 + row) * (size_t)K + (vb ? k : 0); \
        uint32_t sa = bb + (uint32_t)(row * LDT + c * 4) * 2; \
        cp8(sa,            Ah + off, (uint32_t)vb * 2); \
        cp8(sa + E_AL * 2, Al + off, (uint32_t)vb * 2); \
    } \
    for (int i = tid; i < 1024; i += 256) { \
        int row = i >> 4, c = i & 15; \
        int k = kbase + c * 4; \
        int vb = K - k; vb = vb < 0 ? 0 : (vb > 4 ? 4 : vb); \
        if (n0 + row >= N) vb = 0; \
        size_t off = (size_t)(n0 + (vb ? row : 0)) * K + (vb ? k : 0); \
        uint32_t sa = bb + (uint32_t)(E_BH + row * LDT + c * 4) * 2; \
        cp8(sa, Bh + off, (uint32_t)vb * 2); \
    } \
} while (0)

    G_STAGE(0, 0);
    cp_commit();
    for (int kc = 0; kc < nch; kc++) {
        const int cur = kc & 1;
        if (kc + 1 < nch) { G_STAGE(cur ^ 1, kc + 1); cp_commit(); cp_wait<1>(); }
        else cp_wait<0>();
        __syncthreads();

        __half* bA = sm + cur * BUF_E;
#pragma unroll
        for (int ks = 0; ks < 4; ks++) {
            const int kb = ks * 16;
            uint32_t aH[2][4], aL[2][4], bH[4][2];
#pragma unroll
            for (int mi = 0; mi < 2; mi++) {
                int r = wm * 32 + mi * 16 + aRow;
                uint32_t adr = smem_u32(bA + r * LDT + kb + aColOff);
                ldsm_x4(aH[mi], adr);
                ldsm_x4(aL[mi], adr + E_AL * 2);
            }
#pragma unroll
            for (int nf = 0; nf < 2; nf++) {
                int r = wn * 32 + nf * 16 + bRow;
                uint32_t adr = smem_u32(bA + E_BH + r * LDT + kb + bColOff);
                uint32_t t[4];
                ldsm_x4(t, adr);
                bH[nf*2][0] = t[0]; bH[nf*2][1] = t[1];
                bH[nf*2+1][0] = t[2]; bH[nf*2+1][1] = t[3];
            }
#pragma unroll
            for (int mi = 0; mi < 2; mi++)
#pragma unroll
                for (int ni = 0; ni < 4; ni++) {
                    mma16816(acc[mi][ni], aH[mi], bH[ni]);
                    mma16816(acc[mi][ni], aL[mi], bH[ni]);
                }
        }
        __syncthreads();
    }
#undef G_STAGE

#pragma unroll
    for (int mi = 0; mi < 2; mi++)
#pragma unroll
        for (int hh = 0; hh < 2; hh++) {
            size_t row = m0 + wm * 32 + mi * 16 + (lane >> 2) + hh * 8;
            int bb = (int)(row >> 16);
#pragma unroll
            for (int ni = 0; ni < 4; ni++) {
                int n_ = n0 + wn * 32 + ni * 8 + (lane & 3) * 2;
                if (n_ >= N) continue;
                float v0 = acc[mi][ni][hh * 2 + 0] + bias[n_];
                float v1 = acc[mi][ni][hh * 2 + 1] + bias[n_ + 1];
                size_t o = row * (size_t)N + n_;
                if (MODE == 0) {
                    *(float2*)(outf + o) = make_float2(v0, v1);
                } else if (MODE == 1) {
                    float gg0 = gelu_f(v0), gg1 = gelu_f(v1);
                    __half h0, l0, h1, l1;
                    split2h(gg0, h0, l0); split2h(gg1, h1, l1);
                    *(__half2*)(outh + o) = __halves2half2(h0, h1);
                    *(__half2*)(outl + o) = __halves2half2(l0, l1);
                } else if (MODE == 2) {
                    float2 xv = *(const float2*)(aux1 + o);
                    float2 yv = *(const float2*)(aux2 + o);
                    *(float2*)(outf + o) = make_float2(
                        xv.x + v0 + yv.x * ga[bb * CC + n_],
                        xv.y + v1 + yv.y * ga[bb * CC + n_ + 1]);
                } else {
                    float2 xm = *(const float2*)(aux1 + o);
                    *(float2*)(outf + o) = make_float2(xm.x + v0, xm.y + v1);
                }
            }
        }
}

// ---------------- implicit-GEMM 3x3 conv, single-pass fp16 ----------------
// CMODE 0: gelu(+bias) -> fp16 (hi only) | 1: fp32 +bias
template<int KSRC, int NCH, int OCT, int CMODE>
__global__ __launch_bounds__(256)
void conv_mma(const __half* __restrict__ Ah, const __half* __restrict__ Wh,
              const float* __restrict__ bias,
              float* __restrict__ outf, __half* __restrict__ outh)
{
    extern __shared__ __half sm[];
    const uint32_t sbase = smem_u32(sm);
    const int tid  = threadIdx.x;
    const int warp = tid >> 5, lane = tid & 31;
    const int wm = warp >> 1, wn = warp & 1;
    const size_t m0 = (size_t)blockIdx.y * 128;
    const int oc0 = blockIdx.x * 60;

    float acc[2][4][4];
#pragma unroll
    for (int i = 0; i < 2; i++)
#pragma unroll
        for (int j = 0; j < 4; j++)
#pragma unroll
            for (int c = 0; c < 4; c++) acc[i][j][c] = 0.f;

    const int aRow = (lane & 15), aColOff = (lane >> 4) << 3;
    const int bRow = ((lane >> 4) << 3) + (lane & 7), bColOff = ((lane >> 3) & 1) << 3;
    const int NIT = 9 * NCH;

#define C_STAGE(buf, it) do { \
    const int tap = (it) / NCH; \
    const int kbase = ((it) % NCH) * 64; \
    const int dr = tap / 3 - 1, dc = tap % 3 - 1; \
    const int toff = dr * 256 + dc; \
    const uint32_t bb = sbase + (uint32_t)(buf) * (CBUF * 2); \
    for (int i = tid; i < 2048; i += 256) { \
        int row = i >> 4, c = i & 15; \
        int t = (int)(m0 + row); \
        int hh2 = (t >> 8) & 255, ww2 = t & 255; \
        int k = kbase + c * 4; \
        int vb = KSRC - k; vb = vb < 0 ? 0 : (vb > 4 ? 4 : vb); \
        if ((unsigned)(hh2 + dr) >= 256u || (unsigned)(ww2 + dc) >= 256u) vb = 0; \
        size_t off = vb ? ((size_t)(t + toff) * KSRC + k) : 0; \
        uint32_t sa = bb + (uint32_t)(row * LDT + c * 4) * 2; \
        cp8(sa, Ah + off, (uint32_t)vb * 2); \
    } \
    for (int i = tid; i < 1024; i += 256) { \
        int n = i >> 4, c = i & 15; \
        int k = kbase + c * 4; \
        int vb = KSRC - k; vb = vb < 0 ? 0 : (vb > 4 ? 4 : vb); \
        if (n >= 60) vb = 0; \
        size_t off = vb ? ((size_t)tap * OCT * KSRC + (size_t)(oc0 + n) * KSRC + k) : 0; \
        uint32_t sa = bb + (uint32_t)(CE_B + n * LDT + c * 4) * 2; \
        cp8(sa, Wh + off, (uint32_t)vb * 2); \
    } \
} while (0)

    C_STAGE(0, 0);
    cp_commit();
    for (int it = 0; it < NIT; it++) {
        const int cur = it & 1;
        if (it + 1 < NIT) { C_STAGE(cur ^ 1, it + 1); cp_commit(); cp_wait<1>(); }
        else cp_wait<0>();
        __syncthreads();

        __half* bA = sm + cur * CBUF;
#pragma unroll
        for (int ks = 0; ks < 4; ks++) {
            const int kbb = ks * 16;
            uint32_t aH[2][4], bH[4][2];
#pragma unroll
            for (int mi = 0; mi < 2; mi++) {
                int r = wm * 32 + mi * 16 + aRow;
                ldsm_x4(aH[mi], smem_u32(bA + r * LDT + kbb + aColOff));
            }
#pragma unroll
            for (int nf = 0; nf < 2; nf++) {
                int r = wn * 32 + nf * 16 + bRow;
                uint32_t t4[4];
                ldsm_x4(t4, smem_u32(bA + CE_B + r * LDT + kbb + bColOff));
                bH[nf*2][0] = t4[0]; bH[nf*2][1] = t4[1];
                bH[nf*2+1][0] = t4[2]; bH[nf*2+1][1] = t4[3];
            }
#pragma unroll
            for (int mi = 0; mi < 2; mi++)
#pragma unroll
                for (int ni = 0; ni < 4; ni++)
                    mma16816(acc[mi][ni], aH[mi], bH[ni]);
        }
        __syncthreads();
    }
#undef C_STAGE

#pragma unroll
    for (int mi = 0; mi < 2; mi++)
#pragma unroll
        for (int hh = 0; hh < 2; hh++) {
            size_t row = m0 + wm * 32 + mi * 16 + (lane >> 2) + hh * 8;
#pragma unroll
            for (int ni = 0; ni < 4; ni++) {
                int n_ = wn * 32 + ni * 8 + (lane & 3) * 2;
                if (n_ >= 60) continue;
                int oc = oc0 + n_;
                float v0 = acc[mi][ni][hh * 2 + 0] + bias[oc];
                float v1 = acc[mi][ni][hh * 2 + 1] + bias[oc + 1];
                size_t o = row * (size_t)OCT + oc;
                if (CMODE == 0) {
                    *(__half2*)(outh + o) = __halves2half2(
                        __float2half_rn(gelu_f(v0)), __float2half_rn(gelu_f(v1)));
                } else {
                    *(float2*)(outf + o) = make_float2(v0, v1);
                }
            }
        }
}

// ---------------- channel pooling (stage 1) ----------------
__global__ __launch_bounds__(256)
void pool_partial_kernel(const float* __restrict__ y, float* __restrict__ pp) {
    __shared__ float s[64 * CC];
    int tid = threadIdx.x;
    int blk = blockIdx.x;
    size_t base = (size_t)blk * 256 * CC;
    float acc = 0.f;
    for (int it = 0; it < 4; it++) {
        __syncthreads();
        const float4* src = (const float4*)(y + base + (size_t)it * 64 * CC);
        float4* d4 = (float4*)s;
        for (int i = tid; i < 64 * CC / 4; i += 256) d4[i] = src[i];
        __syncthreads();
        if (tid < CC) {
#pragma unroll
            for (int t = 0; t < 64; t++) acc += s[t * CC + tid];
        }
    }
    if (tid < CC) pp[blk * CC + tid] = acc;
}

// ---------------- channel attention ----------------
__global__ void ca_kernel(const float* __restrict__ poolp,
                          const float* __restrict__ w1, const float* __restrict__ b1,
                          const float* __restrict__ w2, const float* __restrict__ b2,
                          float* __restrict__ ga) {
    int b = blockIdx.x;
    int t = threadIdx.x;
    __shared__ float mean[CC];
    __shared__ float sq[CAD];
    if (t < CC) {
        float a = 0.f;
        for (int k = 0; k < 256; k++) a += poolp[(size_t)(b * 256 + k) * CC + t];
        mean[t] = a * (1.f / 65536.f);
    }
    __syncthreads();
    if (t < CAD) {
        float a = b1[t];
        for (int c = 0; c < CC; c++) a += mean[c] * w1[t * CC + c];
        sq[t] = fmaxf(a, 0.f);
    }
    __syncthreads();
    if (t < CC) {
        float a = b2[t];
#pragma unroll
        for (int j = 0; j < CAD; j++) a += sq[j] * w2[t * CAD + j];
        ga[b * CC + t] = 0.01f / (1.f + expf(-a));
    }
}

// ---------------- window attention (fp16 hi/lo out) ----------------
__global__ __launch_bounds__(256)
void attn_kernel(const float* __restrict__ qkv, const float* __restrict__ bias_table,
                 const int* __restrict__ rpi,
                 __half* __restrict__ atth, __half* __restrict__ attl) {
    extern __shared__ float smf[];
    float* sQ = smf;
    float* sK = sQ + 64 * 33;
    float* sV = sK + 64 * 33;
    float* sA = sV + 64 * 33;
    int*   sR = (int*)(sA + 64 * 66);

    const int tid = threadIdx.x;
    const int b   = blockIdx.x >> 10;
    const int win = blockIdx.x & 1023;
    const int wr  = win >> 5, wc = win & 31;
    const int row0 = b * HW + (wr * 8) * 256 + wc * 8;

    for (int idx = tid; idx < 4096; idx += 256) sR[idx] = rpi[idx];

    const float scale = 0.18257418583505536f;
    for (int h = 0; h < HEADS; h++) {
        __syncthreads();
        for (int idx = tid; idx < 1920; idx += 256) {
            int i = idx / 30, d = idx % 30;
            int gt = row0 + (i >> 3) * 256 + (i & 7);
            const float* p = qkv + (size_t)gt * 540 + h * HD + d;
            sQ[i * 33 + d] = p[0] * scale;
            sK[i * 33 + d] = p[180];
            sV[i * 33 + d] = p[360];
        }
        __syncthreads();
        for (int idx = tid; idx < 2048; idx += 256) {
            int j = idx & 63, ip = idx >> 6;
            int i0 = ip * 2, i1 = i0 + 1;
            float s0 = bias_table[sR[i0 * 64 + j] * HEADS + h];
            float s1 = bias_table[sR[i1 * 64 + j] * HEADS + h];
            const float* q0 = sQ + i0 * 33;
            const float* q1 = sQ + i1 * 33;
            const float* kp = sK + j * 33;
#pragma unroll
            for (int d = 0; d < HD; d++) {
                float kv = kp[d];
                s0 += q0[d] * kv; s1 += q1[d] * kv;
            }
            sA[i0 * 66 + j] = s0; sA[i1 * 66 + j] = s1;
        }
        __syncthreads();
        {
            int w = tid >> 5, lane = tid & 31;
            for (int rrow = w; rrow < 64; rrow += 8) {
                float* row = sA + rrow * 66;
                float v0 = row[lane], v1 = row[lane + 32];
                float m = fmaxf(v0, v1);
#pragma unroll
                for (int o = 16; o > 0; o >>= 1) m = fmaxf(m, __shfl_xor_sync(0xffffffffu, m, o));
                float e0 = expf(v0 - m), e1 = expf(v1 - m);
                float s = e0 + e1;
#pragma unroll
                for (int o = 16; o > 0; o >>= 1) s += __shfl_xor_sync(0xffffffffu, s, o);
                float inv = 1.f / s;
                row[lane] = e0 * inv; row[lane + 32] = e1 * inv;
            }
        }
        __syncthreads();
        for (int idx = tid; idx < 960; idx += 256) {
            int d = idx % 30, ip = idx / 30;
            int i0 = ip * 2, i1 = i0 + 1;
            const float* a0 = sA + i0 * 66;
            const float* a1 = sA + i1 * 66;
            float o0 = 0.f, o1 = 0.f;
#pragma unroll 8
            for (int j = 0; j < 64; j++) {
                float vv = sV[j * 33 + d];
                o0 += a0[j] * vv; o1 += a1[j] * vv;
            }
            int gt0 = row0 + (i0 >> 3) * 256 + (i0 & 7);
            int gt1 = row0 + (i1 >> 3) * 256 + (i1 & 7);
            size_t p0 = (size_t)gt0 * CC + h * HD + d;
            size_t p1 = (size_t)gt1 * CC + h * HD + d;
            __half hh, ll;
            split2h(o0, hh, ll); atth[p0] = hh; attl[p0] = ll;
            split2h(o1, hh, ll); atth[p1] = hh; attl[p1] = ll;
        }
    }
}

// ---------------- host launch ----------------
extern "C" void kernel_launch(void* const* d_in, const int* in_sizes, int n_in,
                              void* d_out, int out_size) {
    const float* x          = (const float*)d_in[0];
    const float* ln1_g      = (const float*)d_in[1];
    const float* ln1_b      = (const float*)d_in[2];
    const float* qkv_w      = (const float*)d_in[3];
    const float* qkv_b      = (const float*)d_in[4];
    const float* bias_table = (const float*)d_in[5];
    const float* proj_w     = (const float*)d_in[6];
    const float* proj_b     = (const float*)d_in[7];
    const float* cab_w1     = (const float*)d_in[8];
    const float* cab_b1     = (const float*)d_in[9];
    const float* cab_w2     = (const float*)d_in[10];
    const float* cab_b2     = (const float*)d_in[11];
    const float* ca_w1      = (const float*)d_in[12];
    const float* ca_b1      = (const float*)d_in[13];
    const float* ca_w2      = (const float*)d_in[14];
    const float* ca_b2      = (const float*)d_in[15];
    const float* ln2_g      = (const float*)d_in[16];
    const float* ln2_b      = (const float*)d_in[17];
    const float* fc1_w      = (const float*)d_in[18];
    const float* fc1_b      = (const float*)d_in[19];
    const float* fc2_w      = (const float*)d_in[20];
    const float* fc2_b      = (const float*)d_in[21];
    const int*   rpi        = (const int*)d_in[22];
    float* out = (float*)d_out;

    float *p_qkv, *p_y, *p_xmid, *p_poolp, *p_a;
    __half *p_xnh, *p_xnl, *p_c1h, *p_atth, *p_attl, *p_hh, *p_hl;
    __half *p_wqh, *p_wph, *p_wf1h, *p_wf2h, *p_w1th, *p_w2th;
    cudaGetSymbolAddress((void**)&p_qkv,   g_qkv);
    cudaGetSymbolAddress((void**)&p_y,     g_y);
    cudaGetSymbolAddress((void**)&p_xmid,  g_xmid);
    cudaGetSymbolAddress((void**)&p_poolp, g_poolp);
    cudaGetSymbolAddress((void**)&p_a,     g_a);
    cudaGetSymbolAddress((void**)&p_xnh,   g_xnh);
    cudaGetSymbolAddress((void**)&p_xnl,   g_xnl);
    cudaGetSymbolAddress((void**)&p_c1h,   g_c1h);
    cudaGetSymbolAddress((void**)&p_atth,  g_atth);
    cudaGetSymbolAddress((void**)&p_attl,  g_attl);
    cudaGetSymbolAddress((void**)&p_hh,    g_hh);
    cudaGetSymbolAddress((void**)&p_hl,    g_hl);
    cudaGetSymbolAddress((void**)&p_wqh,   g_wqh);
    cudaGetSymbolAddress((void**)&p_wph,   g_wph);
    cudaGetSymbolAddress((void**)&p_wf1h,  g_wf1h);
    cudaGetSymbolAddress((void**)&p_wf2h,  g_wf2h);
    cudaGetSymbolAddress((void**)&p_w1th,  g_w1th);
    cudaGetSymbolAddress((void**)&p_w2th,  g_w2th);

    const int smem_attn = (3 * 64 * 33 + 64 * 66) * 4 + 4096 * 4;

    cudaFuncSetAttribute(attn_kernel,  cudaFuncAttributeMaxDynamicSharedMemorySize, smem_attn);
    cudaFuncSetAttribute(mma_gemm<0>, cudaFuncAttributeMaxDynamicSharedMemorySize, SMEM_MMA);
    cudaFuncSetAttribute(mma_gemm<1>, cudaFuncAttributeMaxDynamicSharedMemorySize, SMEM_MMA);
    cudaFuncSetAttribute(mma_gemm<2>, cudaFuncAttributeMaxDynamicSharedMemorySize, SMEM_MMA);
    cudaFuncSetAttribute(mma_gemm<3>, cudaFuncAttributeMaxDynamicSharedMemorySize, SMEM_MMA);
    cudaFuncSetAttribute((conv_mma<CC, 3, C1D, 0>), cudaFuncAttributeMaxDynamicSharedMemorySize, SMEM_CONV);
    cudaFuncSetAttribute((conv_mma<C1D, 1, CC, 1>), cudaFuncAttributeMaxDynamicSharedMemorySize, SMEM_CONV);

    // launch order chosen so ncu (-s 5 -c 1) profiles the qkv GEMM (launch #6)
    // 1. weight prep (single fused kernel)
    prep_weights<<<(NPREP + 255) / 256, 256>>>(qkv_w, proj_w, fc1_w, fc2_w, cab_w1, cab_w2,
                                               p_wqh, p_wph, p_wf1h, p_wf2h, p_w1th, p_w2th);
    // 2. LN1
    ln_kernel<<<NTOK / 8, 256>>>(x, ln1_g, ln1_b, p_xnh, p_xnl, NTOK);
    // 3-4. conv branch (single-pass fp16 implicit GEMM)
    conv_mma<CC, 3, C1D, 0><<<dim3(1, 2048), 256, SMEM_CONV>>>(
        p_xnh, p_w1th, cab_b1, nullptr, p_c1h);
    conv_mma<C1D, 1, CC, 1><<<dim3(3, 2048), 256, SMEM_CONV>>>(
        p_c1h, p_w2th, cab_b2, p_y, nullptr);
    // 5. pooling
    pool_partial_kernel<<<1024, 256>>>(p_y, p_poolp);
    // 6. QKV GEMM (2-pass fp16)
    mma_gemm<0><<<dim3(9, 2048), 256, SMEM_MMA>>>(p_xnh, p_xnl, p_wqh, qkv_b,
                                                  nullptr, nullptr, nullptr,
                                                  p_qkv, nullptr, nullptr, 540, CC);
    // 7. channel attention
    ca_kernel<<<BATCH, 192>>>(p_poolp, ca_w1, ca_b1, ca_w2, ca_b2, p_a);
    // 8. window attention
    attn_kernel<<<NWIN, 256, smem_attn>>>(p_qkv, bias_table, rpi, p_atth, p_attl);
    // 9. proj + residual + conv add
    mma_gemm<2><<<dim3(3, 2048), 256, SMEM_MMA>>>(p_atth, p_attl, p_wph, proj_b,
                                                  x, p_y, p_a,
                                                  p_xmid, nullptr, nullptr, CC, CC);
    // 10-12. MLP
    ln_kernel<<<NTOK / 8, 256>>>(p_xmid, ln2_g, ln2_b, p_xnh, p_xnl, NTOK);
    mma_gemm<1><<<dim3(12, 2048), 256, SMEM_MMA>>>(p_xnh, p_xnl, p_wf1h, fc1_b,
                                                   nullptr, nullptr, nullptr,
                                                   nullptr, p_hh, p_hl, FF, CC);
    mma_gemm<3><<<dim3(3, 2048), 256, SMEM_MMA>>>(p_hh, p_hl, p_wf2h, fc2_b,
                                                  p_xmid, nullptr, nullptr,
                                                  out, nullptr, nullptr, CC, FF);
}

// round 16
// speedup vs baseline: 1.7005x; 1.1993x over previous
#include <cuda_runtime.h>
#include <cuda_fp16.h>
#include <math.h>
#include <stdint.h>

// ---------------- Problem constants ----------------
#define BATCH   4
#define HW      65536
#define CC      180
#define KP      192            // padded K for C=180
#define C1D     60
#define C1P     64             // padded K for C=60
#define CAD     6
#define FF      720
#define FFP     768            // padded K for C=720
#define HEADS   6
#define HD      30
#define NTOK    262144
#define NWIN    4096

// ---------------- Scratch (zero-initialized; pad regions never written) ----------------
__device__ float g_qkv [(size_t)NTOK * 540];
__device__ float g_y   [NTOK * CC];
__device__ float g_xmid[NTOK * CC];
__device__ float g_poolp[1024 * CC];
__device__ float g_a   [BATCH * CC];

__device__ __half g_xnh[(size_t)NTOK * KP],  g_xnl[(size_t)NTOK * KP];
__device__ __half g_c1h[(size_t)NTOK * C1P];
__device__ __half g_atth[(size_t)NTOK * KP], g_attl[(size_t)NTOK * KP];
__device__ __half g_hh[(size_t)NTOK * FFP], g_hl[(size_t)NTOK * FFP];
__device__ __half g_wqh[540 * KP];
__device__ __half g_wph[CC * KP];
__device__ __half g_wf1h[FF * KP];
__device__ __half g_wf2h[CC * FFP];
__device__ __half g_w1th[9 * C1D * KP];    // [tap][oc][ic]
__device__ __half g_w2th[9 * CC * C1P];    // [tap][oc][ic]

__device__ __forceinline__ float gelu_f(float x) {
    return 0.5f * x * (1.0f + erff(x * 0.70710678118654752f));
}
__device__ __forceinline__ void split2h(float f, __half& h, __half& l) {
    h = __float2half_rn(f);
    l = __float2half_rn(f - __half2float(h));
}
__device__ __forceinline__ uint32_t smem_u32(const void* p) {
    uint32_t a;
    asm("{ .reg .u64 t; cvta.to.shared.u64 t, %1; cvt.u32.u64 %0, t; }" : "=r"(a) : "l"(p));
    return a;
}
__device__ __forceinline__ void ldsm_x4(uint32_t* r, uint32_t addr) {
    asm volatile("ldmatrix.sync.aligned.m8n8.x4.shared.b16 {%0,%1,%2,%3}, [%4];"
        : "=r"(r[0]), "=r"(r[1]), "=r"(r[2]), "=r"(r[3]) : "r"(addr));
}
__device__ __forceinline__ void mma16816(float* c, const uint32_t* a, const uint32_t* b) {
    asm volatile("mma.sync.aligned.m16n8k16.row.col.f32.f16.f16.f32 "
        "{%0,%1,%2,%3}, {%4,%5,%6,%7}, {%8,%9}, {%0,%1,%2,%3};"
        : "+f"(c[0]), "+f"(c[1]), "+f"(c[2]), "+f"(c[3])
        : "r"(a[0]), "r"(a[1]), "r"(a[2]), "r"(a[3]), "r"(b[0]), "r"(b[1]));
}
__device__ __forceinline__ void cp16(uint32_t saddr, const void* g, uint32_t bytes) {
    asm volatile("cp.async.cg.shared.global [%0], [%1], 16, %2;"
        :: "r"(saddr), "l"(g), "r"(bytes));
}
__device__ __forceinline__ void cp_commit() { asm volatile("cp.async.commit_group;"); }
template<int N> __device__ __forceinline__ void cp_wait() {
    asm volatile("cp.async.wait_group %0;" :: "n"(N));
}

// ---------------- fused weight prep (fp32 -> fp16, padded strides) ----------------
#define NWQ  (540*CC)
#define NWP  (CC*CC)
#define NWF1 (FF*CC)
#define NWF2 (CC*FF)
#define NW1  (9*C1D*CC)
#define NW2  (9*CC*C1D)
__global__ void prep_weights(const float* __restrict__ wq, const float* __restrict__ wp,
                             const float* __restrict__ wf1, const float* __restrict__ wf2,
                             const float* __restrict__ cw1, const float* __restrict__ cw2,
                             __half* __restrict__ dq, __half* __restrict__ dp,
                             __half* __restrict__ df1, __half* __restrict__ df2,
                             __half* __restrict__ d1t, __half* __restrict__ d2t) {
    int i = blockIdx.x * 256 + threadIdx.x;
    if (i < NWQ) { dq[(i / CC) * KP + i % CC] = __float2half_rn(wq[i]); return; }
    i -= NWQ;
    if (i < NWP) { dp[(i / CC) * KP + i % CC] = __float2half_rn(wp[i]); return; }
    i -= NWP;
    if (i < NWF1) { df1[(i / CC) * KP + i % CC] = __float2half_rn(wf1[i]); return; }
    i -= NWF1;
    if (i < NWF2) { df2[(i / FF) * FFP + i % FF] = __float2half_rn(wf2[i]); return; }
    i -= NWF2;
    if (i < NW1) {
        int tap = i % 9, ic = (i / 9) % CC, oc = i / (9 * CC);
        d1t[(size_t)tap * C1D * KP + (size_t)oc * KP + ic] = __float2half_rn(cw1[i]);
        return;
    }
    i -= NW1;
    if (i < NW2) {
        int tap = i % 9, ic = (i / 9) % C1D, oc = i / (9 * C1D);
        d2t[(size_t)tap * CC * C1P + (size_t)oc * C1P + ic] = __float2half_rn(cw2[i]);
    }
}
#define NPREP (NWQ + NWP + NWF1 + NWF2 + NW1 + NW2)

// ---------------- LayerNorm: fp16 hi/lo (padded stride KP, zeros in pad) ----------------
__global__ void ln_kernel(const float* __restrict__ in, const float* __restrict__ g,
                          const float* __restrict__ bt,
                          __half* __restrict__ oh, __half* __restrict__ ol,
                          int ntok) {
    int gwarp = (blockIdx.x * blockDim.x + threadIdx.x) >> 5;
    int lane  = threadIdx.x & 31;
    if (gwarp >= ntok) return;
    const float* p = in + (size_t)gwarp * CC;
    float v[6]; float s = 0.f, s2 = 0.f;
#pragma unroll
    for (int k = 0; k < 6; k++) {
        int c = lane + 32 * k;
        float xv = (c < CC) ? p[c] : 0.f;
        v[k] = xv; s += xv; s2 += xv * xv;
    }
#pragma unroll
    for (int o = 16; o > 0; o >>= 1) {
        s  += __shfl_xor_sync(0xffffffffu, s,  o);
        s2 += __shfl_xor_sync(0xffffffffu, s2, o);
    }
    float mean = s * (1.f / CC);
    float var  = s2 * (1.f / CC) - mean * mean;
    float inv  = rsqrtf(var + 1e-5f);
    size_t base = (size_t)gwarp * KP;
#pragma unroll
    for (int k = 0; k < 6; k++) {
        int c = lane + 32 * k;    // 0..191 — covers pad with zeros
        float y = (c < CC) ? ((v[k] - mean) * inv * g[c] + bt[c]) : 0.f;
        __half h, l; split2h(y, h, l);
        oh[base + c] = h; ol[base + c] = l;
    }
}

// ---------------- tile geometry ----------------
#define LDT 72
#define E_AL 9216
#define E_BH 18432
#define BUF_E 23040
#define SMEM_MMA (2 * BUF_E * 2)    // 92160 B
#define CE_B 9216
#define CBUF 13824
#define SMEM_CONV (2 * CBUF * 2)    // 55296 B

// ---------------- fp16 mma.sync GEMM, 2-pass (A hi/lo, B hi), cp16 staging ----------------
// MODE 0: fp32 +bias | 1: gelu(+bias)->fp16 hi/lo (stride ldo) | 2: proj epi | 3: fc2 epi
template<int MODE>
__global__ __launch_bounds__(256)
void mma_gemm(const __half* __restrict__ Ah, const __half* __restrict__ Al,
              const __half* __restrict__ Bh,
              const float* __restrict__ bias,
              const float* __restrict__ aux1, const float* __restrict__ aux2,
              const float* __restrict__ ga,
              float* __restrict__ outf, __half* __restrict__ outh,
              __half* __restrict__ outl, int N, int K, int ldo)
{
    extern __shared__ __half sm[];
    const uint32_t sbase = smem_u32(sm);
    const int tid  = threadIdx.x;
    const int warp = tid >> 5, lane = tid & 31;
    const int wm = warp >> 1, wn = warp & 1;
    const size_t m0 = (size_t)blockIdx.y * 128;
    const int n0 = blockIdx.x * 64;

    float acc[2][4][4];
#pragma unroll
    for (int i = 0; i < 2; i++)
#pragma unroll
        for (int j = 0; j < 4; j++)
#pragma unroll
            for (int c = 0; c < 4; c++) acc[i][j][c] = 0.f;

    const int aRow = (lane & 15), aColOff = (lane >> 4) << 3;
    const int bRow = ((lane >> 4) << 3) + (lane & 7), bColOff = ((lane >> 3) & 1) << 3;
    const int nch = K >> 6;

#define G_STAGE(buf, kc) do { \
    const int kbase = (kc) * 64; \
    const uint32_t bb = sbase + (uint32_t)(buf) * (BUF_E * 2); \
    for (int i = tid; i < 1024; i += 256) { \
        int row = i >> 3, c = i & 7; \
        size_t off = (m0 + row) * (size_t)K + kbase + c * 8; \
        uint32_t sa = bb + (uint32_t)(row * LDT + c * 8) * 2; \
        cp16(sa,            Ah + off, 16); \
        cp16(sa + E_AL * 2, Al + off, 16); \
    } \
    for (int i = tid; i < 512; i += 256) { \
        int row = i >> 3, c = i & 7; \
        int n_ = n0 + row; \
        uint32_t vb = (n_ < N) ? 16u : 0u; \
        size_t off = (n_ < N) ? ((size_t)n_ * K + kbase + c * 8) : 0; \
        uint32_t sa = bb + (uint32_t)(E_BH + row * LDT + c * 8) * 2; \
        cp16(sa, Bh + off, vb); \
    } \
} while (0)

    G_STAGE(0, 0);
    cp_commit();
    for (int kc = 0; kc < nch; kc++) {
        const int cur = kc & 1;
        if (kc + 1 < nch) { G_STAGE(cur ^ 1, kc + 1); cp_commit(); cp_wait<1>(); }
        else cp_wait<0>();
        __syncthreads();

        const uint32_t bb = sbase + (uint32_t)cur * (BUF_E * 2);
        const uint32_t aBase = bb + (uint32_t)((wm * 32 + aRow) * LDT + aColOff) * 2;
        const uint32_t bBase = bb + (uint32_t)(E_BH + (wn * 32 + bRow) * LDT + bColOff) * 2;
#pragma unroll
        for (int ks = 0; ks < 4; ks++) {
            const uint32_t kb2 = (uint32_t)(ks * 16) * 2;
            uint32_t aH[2][4], aL[2][4], bH[4][2];
#pragma unroll
            for (int mi = 0; mi < 2; mi++) {
                uint32_t adr = aBase + kb2 + (uint32_t)(mi * 16 * LDT) * 2;
                ldsm_x4(aH[mi], adr);
                ldsm_x4(aL[mi], adr + E_AL * 2);
            }
#pragma unroll
            for (int nf = 0; nf < 2; nf++) {
                uint32_t adr = bBase + kb2 + (uint32_t)(nf * 16 * LDT) * 2;
                uint32_t t[4];
                ldsm_x4(t, adr);
                bH[nf*2][0] = t[0]; bH[nf*2][1] = t[1];
                bH[nf*2+1][0] = t[2]; bH[nf*2+1][1] = t[3];
            }
#pragma unroll
            for (int mi = 0; mi < 2; mi++)
#pragma unroll
                for (int ni = 0; ni < 4; ni++) {
                    mma16816(acc[mi][ni], aH[mi], bH[ni]);
                    mma16816(acc[mi][ni], aL[mi], bH[ni]);
                }
        }
        __syncthreads();
    }
#undef G_STAGE

#pragma unroll
    for (int mi = 0; mi < 2; mi++)
#pragma unroll
        for (int hh = 0; hh < 2; hh++) {
            size_t row = m0 + wm * 32 + mi * 16 + (lane >> 2) + hh * 8;
            int bb = (int)(row >> 16);
#pragma unroll
            for (int ni = 0; ni < 4; ni++) {
                int n_ = n0 + wn * 32 + ni * 8 + (lane & 3) * 2;
                if (n_ >= N) continue;
                float v0 = acc[mi][ni][hh * 2 + 0] + bias[n_];
                float v1 = acc[mi][ni][hh * 2 + 1] + bias[n_ + 1];
                if (MODE == 0) {
                    size_t o = row * (size_t)N + n_;
                    *(float2*)(outf + o) = make_float2(v0, v1);
                } else if (MODE == 1) {
                    size_t o = row * (size_t)ldo + n_;
                    float gg0 = gelu_f(v0), gg1 = gelu_f(v1);
                    __half h0, l0, h1, l1;
                    split2h(gg0, h0, l0); split2h(gg1, h1, l1);
                    *(__half2*)(outh + o) = __halves2half2(h0, h1);
                    *(__half2*)(outl + o) = __halves2half2(l0, l1);
                } else if (MODE == 2) {
                    size_t o = row * (size_t)N + n_;
                    float2 xv = *(const float2*)(aux1 + o);
                    float2 yv = *(const float2*)(aux2 + o);
                    *(float2*)(outf + o) = make_float2(
                        xv.x + v0 + yv.x * ga[bb * CC + n_],
                        xv.y + v1 + yv.y * ga[bb * CC + n_ + 1]);
                } else {
                    size_t o = row * (size_t)N + n_;
                    float2 xm = *(const float2*)(aux1 + o);
                    *(float2*)(outf + o) = make_float2(xm.x + v0, xm.y + v1);
                }
            }
        }
}

// ---------------- implicit-GEMM 3x3 conv, single-pass fp16, cp16 staging ----------------
// KSP: padded K stride; CMODE 0: gelu(+bias)->fp16 (stride OSTR) | 1: fp32 +bias (stride OSTR)
template<int KSP, int OSTR, int CMODE>
__global__ __launch_bounds__(256)
void conv_mma(const __half* __restrict__ Ah, const __half* __restrict__ Wh,
              const float* __restrict__ bias,
              float* __restrict__ outf, __half* __restrict__ outh)
{
    extern __shared__ __half sm[];
    const uint32_t sbase = smem_u32(sm);
    const int tid  = threadIdx.x;
    const int warp = tid >> 5, lane = tid & 31;
    const int wm = warp >> 1, wn = warp & 1;
    const size_t m0 = (size_t)blockIdx.y * 128;
    const int oc0 = blockIdx.x * 60;
    const int NCH = KSP >> 6;

    float acc[2][4][4];
#pragma unroll
    for (int i = 0; i < 2; i++)
#pragma unroll
        for (int j = 0; j < 4; j++)
#pragma unroll
            for (int c = 0; c < 4; c++) acc[i][j][c] = 0.f;

    const int aRow = (lane & 15), aColOff = (lane >> 4) << 3;
    const int bRow = ((lane >> 4) << 3) + (lane & 7), bColOff = ((lane >> 3) & 1) << 3;
    const int NIT = 9 * NCH;

#define C_STAGE(buf, it) do { \
    const int tap = (it) / NCH; \
    const int kbase = ((it) % NCH) * 64; \
    const int dr = tap / 3 - 1, dc = tap % 3 - 1; \
    const int toff = dr * 256 + dc; \
    const uint32_t bb = sbase + (uint32_t)(buf) * (CBUF * 2); \
    for (int i = tid; i < 1024; i += 256) { \
        int row = i >> 3, c = i & 7; \
        int t = (int)(m0 + row); \
        int hh2 = (t >> 8) & 255, ww2 = t & 255; \
        bool ok = ((unsigned)(hh2 + dr) < 256u) && ((unsigned)(ww2 + dc) < 256u); \
        uint32_t vb = ok ? 16u : 0u; \
        size_t off = ok ? ((size_t)(t + toff) * KSP + kbase + c * 8) : 0; \
        uint32_t sa = bb + (uint32_t)(row * LDT + c * 8) * 2; \
        cp16(sa, Ah + off, vb); \
    } \
    for (int i = tid; i < 512; i += 256) { \
        int n = i >> 3, c = i & 7; \
        uint32_t vb = (n < 60) ? 16u : 0u; \
        size_t off = (n < 60) ? ((size_t)tap * OSTR * KSP + (size_t)(oc0 + n) * KSP + kbase + c * 8) : 0; \
        uint32_t sa = bb + (uint32_t)(CE_B + n * LDT + c * 8) * 2; \
        cp16(sa, Wh + off, vb); \
    } \
} while (0)

    C_STAGE(0, 0);
    cp_commit();
    for (int it = 0; it < NIT; it++) {
        const int cur = it & 1;
        if (it + 1 < NIT) { C_STAGE(cur ^ 1, it + 1); cp_commit(); cp_wait<1>(); }
        else cp_wait<0>();
        __syncthreads();

        const uint32_t bb = sbase + (uint32_t)cur * (CBUF * 2);
        const uint32_t aBase = bb + (uint32_t)((wm * 32 + aRow) * LDT + aColOff) * 2;
        const uint32_t bBase = bb + (uint32_t)(CE_B + (wn * 32 + bRow) * LDT + bColOff) * 2;
#pragma unroll
        for (int ks = 0; ks < 4; ks++) {
            const uint32_t kb2 = (uint32_t)(ks * 16) * 2;
            uint32_t aH[2][4], bH[4][2];
#pragma unroll
            for (int mi = 0; mi < 2; mi++)
                ldsm_x4(aH[mi], aBase + kb2 + (uint32_t)(mi * 16 * LDT) * 2);
#pragma unroll
            for (int nf = 0; nf < 2; nf++) {
                uint32_t t4[4];
                ldsm_x4(t4, bBase + kb2 + (uint32_t)(nf * 16 * LDT) * 2);
                bH[nf*2][0] = t4[0]; bH[nf*2][1] = t4[1];
                bH[nf*2+1][0] = t4[2]; bH[nf*2+1][1] = t4[3];
            }
#pragma unroll
            for (int mi = 0; mi < 2; mi++)
#pragma unroll
                for (int ni = 0; ni < 4; ni++)
                    mma16816(acc[mi][ni], aH[mi], bH[ni]);
        }
        __syncthreads();
    }
#undef C_STAGE

#pragma unroll
    for (int mi = 0; mi < 2; mi++)
#pragma unroll
        for (int hh = 0; hh < 2; hh++) {
            size_t row = m0 + wm * 32 + mi * 16 + (lane >> 2) + hh * 8;
#pragma unroll
            for (int ni = 0; ni < 4; ni++) {
                int n_ = wn * 32 + ni * 8 + (lane & 3) * 2;
                if (n_ >= 60) continue;
                int oc = oc0 + n_;
                float v0 = acc[mi][ni][hh * 2 + 0] + bias[oc];
                float v1 = acc[mi][ni][hh * 2 + 1] + bias[oc + 1];
                if (CMODE == 0) {
                    size_t o = row * (size_t)C1P + oc;   // conv1 out stride 64
                    *(__half2*)(outh + o) = __halves2half2(
                        __float2half_rn(gelu_f(v0)), __float2half_rn(gelu_f(v1)));
                } else {
                    size_t o = row * (size_t)CC + oc;    // conv2 fp32 out stride 180
                    *(float2*)(outf + o) = make_float2(v0, v1);
                }
            }
        }
}

// ---------------- channel pooling (stage 1) ----------------
__global__ __launch_bounds__(256)
void pool_partial_kernel(const float* __restrict__ y, float* __restrict__ pp) {
    __shared__ float s[64 * CC];
    int tid = threadIdx.x;
    int blk = blockIdx.x;
    size_t base = (size_t)blk * 256 * CC;
    float acc = 0.f;
    for (int it = 0; it < 4; it++) {
        __syncthreads();
        const float4* src = (const float4*)(y + base + (size_t)it * 64 * CC);
        float4* d4 = (float4*)s;
        for (int i = tid; i < 64 * CC / 4; i += 256) d4[i] = src[i];
        __syncthreads();
        if (tid < CC) {
#pragma unroll
            for (int t = 0; t < 64; t++) acc += s[t * CC + tid];
        }
    }
    if (tid < CC) pp[blk * CC + tid] = acc;
}

// ---------------- channel attention ----------------
__global__ void ca_kernel(const float* __restrict__ poolp,
                          const float* __restrict__ w1, const float* __restrict__ b1,
                          const float* __restrict__ w2, const float* __restrict__ b2,
                          float* __restrict__ ga) {
    int b = blockIdx.x;
    int t = threadIdx.x;
    __shared__ float mean[CC];
    __shared__ float sq[CAD];
    if (t < CC) {
        float a = 0.f;
        for (int k = 0; k < 256; k++) a += poolp[(size_t)(b * 256 + k) * CC + t];
        mean[t] = a * (1.f / 65536.f);
    }
    __syncthreads();
    if (t < CAD) {
        float a = b1[t];
        for (int c = 0; c < CC; c++) a += mean[c] * w1[t * CC + c];
        sq[t] = fmaxf(a, 0.f);
    }
    __syncthreads();
    if (t < CC) {
        float a = b2[t];
#pragma unroll
        for (int j = 0; j < CAD; j++) a += sq[j] * w2[t * CAD + j];
        ga[b * CC + t] = 0.01f / (1.f + expf(-a));
    }
}

// ---------------- window attention (fp16 hi/lo out, padded stride) ----------------
__global__ __launch_bounds__(256)
void attn_kernel(const float* __restrict__ qkv, const float* __restrict__ bias_table,
                 const int* __restrict__ rpi,
                 __half* __restrict__ atth, __half* __restrict__ attl) {
    extern __shared__ float smf[];
    float* sQ = smf;
    float* sK = sQ + 64 * 33;
    float* sV = sK + 64 * 33;
    float* sA = sV + 64 * 33;
    int*   sR = (int*)(sA + 64 * 66);

    const int tid = threadIdx.x;
    const int b   = blockIdx.x >> 10;
    const int win = blockIdx.x & 1023;
    const int wr  = win >> 5, wc = win & 31;
    const int row0 = b * HW + (wr * 8) * 256 + wc * 8;

    for (int idx = tid; idx < 4096; idx += 256) sR[idx] = rpi[idx];

    const float scale = 0.18257418583505536f;
    for (int h = 0; h < HEADS; h++) {
        __syncthreads();
        for (int idx = tid; idx < 1920; idx += 256) {
            int i = idx / 30, d = idx % 30;
            int gt = row0 + (i >> 3) * 256 + (i & 7);
            const float* p = qkv + (size_t)gt * 540 + h * HD + d;
            sQ[i * 33 + d] = p[0] * scale;
            sK[i * 33 + d] = p[180];
            sV[i * 33 + d] = p[360];
        }
        __syncthreads();
        for (int idx = tid; idx < 2048; idx += 256) {
            int j = idx & 63, ip = idx >> 6;
            int i0 = ip * 2, i1 = i0 + 1;
            float s0 = bias_table[sR[i0 * 64 + j] * HEADS + h];
            float s1 = bias_table[sR[i1 * 64 + j] * HEADS + h];
            const float* q0 = sQ + i0 * 33;
            const float* q1 = sQ + i1 * 33;
            const float* kp = sK + j * 33;
#pragma unroll
            for (int d = 0; d < HD; d++) {
                float kv = kp[d];
                s0 += q0[d] * kv; s1 += q1[d] * kv;
            }
            sA[i0 * 66 + j] = s0; sA[i1 * 66 + j] = s1;
        }
        __syncthreads();
        {
            int w = tid >> 5, lane = tid & 31;
            for (int rrow = w; rrow < 64; rrow += 8) {
                float* row = sA + rrow * 66;
                float v0 = row[lane], v1 = row[lane + 32];
                float m = fmaxf(v0, v1);
#pragma unroll
                for (int o = 16; o > 0; o >>= 1) m = fmaxf(m, __shfl_xor_sync(0xffffffffu, m, o));
                float e0 = expf(v0 - m), e1 = expf(v1 - m);
                float s = e0 + e1;
#pragma unroll
                for (int o = 16; o > 0; o >>= 1) s += __shfl_xor_sync(0xffffffffu, s, o);
                float inv = 1.f / s;
                row[lane] = e0 * inv; row[lane + 32] = e1 * inv;
            }
        }
        __syncthreads();
        for (int idx = tid; idx < 960; idx += 256) {
            int d = idx % 30, ip = idx / 30;
            int i0 = ip * 2, i1 = i0 + 1;
            const float* a0 = sA + i0 * 66;
            const float* a1 = sA + i1 * 66;
            float o0 = 0.f, o1 = 0.f;
#pragma unroll 8
            for (int j = 0; j < 64; j++) {
                float vv = sV[j * 33 + d];
                o0 += a0[j] * vv; o1 += a1[j] * vv;
            }
            int gt0 = row0 + (i0 >> 3) * 256 + (i0 & 7);
            int gt1 = row0 + (i1 >> 3) * 256 + (i1 & 7);
            size_t p0 = (size_t)gt0 * KP + h * HD + d;
            size_t p1 = (size_t)gt1 * KP + h * HD + d;
            __half hh, ll;
            split2h(o0, hh, ll); atth[p0] = hh; attl[p0] = ll;
            split2h(o1, hh, ll); atth[p1] = hh; attl[p1] = ll;
        }
    }
}

// ---------------- host launch ----------------
extern "C" void kernel_launch(void* const* d_in, const int* in_sizes, int n_in,
                              void* d_out, int out_size) {
    const float* x          = (const float*)d_in[0];
    const float* ln1_g      = (const float*)d_in[1];
    const float* ln1_b      = (const float*)d_in[2];
    const float* qkv_w      = (const float*)d_in[3];
    const float* qkv_b      = (const float*)d_in[4];
    const float* bias_table = (const float*)d_in[5];
    const float* proj_w     = (const float*)d_in[6];
    const float* proj_b     = (const float*)d_in[7];
    const float* cab_w1     = (const float*)d_in[8];
    const float* cab_b1     = (const float*)d_in[9];
    const float* cab_w2     = (const float*)d_in[10];
    const float* cab_b2     = (const float*)d_in[11];
    const float* ca_w1      = (const float*)d_in[12];
    const float* ca_b1      = (const float*)d_in[13];
    const float* ca_w2      = (const float*)d_in[14];
    const float* ca_b2      = (const float*)d_in[15];
    const float* ln2_g      = (const float*)d_in[16];
    const float* ln2_b      = (const float*)d_in[17];
    const float* fc1_w      = (const float*)d_in[18];
    const float* fc1_b      = (const float*)d_in[19];
    const float* fc2_w      = (const float*)d_in[20];
    const float* fc2_b      = (const float*)d_in[21];
    const int*   rpi        = (const int*)d_in[22];
    float* out = (float*)d_out;

    float *p_qkv, *p_y, *p_xmid, *p_poolp, *p_a;
    __half *p_xnh, *p_xnl, *p_c1h, *p_atth, *p_attl, *p_hh, *p_hl;
    __half *p_wqh, *p_wph, *p_wf1h, *p_wf2h, *p_w1th, *p_w2th;
    cudaGetSymbolAddress((void**)&p_qkv,   g_qkv);
    cudaGetSymbolAddress((void**)&p_y,     g_y);
    cudaGetSymbolAddress((void**)&p_xmid,  g_xmid);
    cudaGetSymbolAddress((void**)&p_poolp, g_poolp);
    cudaGetSymbolAddress((void**)&p_a,     g_a);
    cudaGetSymbolAddress((void**)&p_xnh,   g_xnh);
    cudaGetSymbolAddress((void**)&p_xnl,   g_xnl);
    cudaGetSymbolAddress((void**)&p_c1h,   g_c1h);
    cudaGetSymbolAddress((void**)&p_atth,  g_atth);
    cudaGetSymbolAddress((void**)&p_attl,  g_attl);
    cudaGetSymbolAddress((void**)&p_hh,    g_hh);
    cudaGetSymbolAddress((void**)&p_hl,    g_hl);
    cudaGetSymbolAddress((void**)&p_wqh,   g_wqh);
    cudaGetSymbolAddress((void**)&p_wph,   g_wph);
    cudaGetSymbolAddress((void**)&p_wf1h,  g_wf1h);
    cudaGetSymbolAddress((void**)&p_wf2h,  g_wf2h);
    cudaGetSymbolAddress((void**)&p_w1th,  g_w1th);
    cudaGetSymbolAddress((void**)&p_w2th,  g_w2th);

    const int smem_attn = (3 * 64 * 33 + 64 * 66) * 4 + 4096 * 4;

    cudaFuncSetAttribute(attn_kernel,  cudaFuncAttributeMaxDynamicSharedMemorySize, smem_attn);
    cudaFuncSetAttribute(mma_gemm<0>, cudaFuncAttributeMaxDynamicSharedMemorySize, SMEM_MMA);
    cudaFuncSetAttribute(mma_gemm<1>, cudaFuncAttributeMaxDynamicSharedMemorySize, SMEM_MMA);
    cudaFuncSetAttribute(mma_gemm<2>, cudaFuncAttributeMaxDynamicSharedMemorySize, SMEM_MMA);
    cudaFuncSetAttribute(mma_gemm<3>, cudaFuncAttributeMaxDynamicSharedMemorySize, SMEM_MMA);
    cudaFuncSetAttribute((conv_mma<KP, C1D, 0>),  cudaFuncAttributeMaxDynamicSharedMemorySize, SMEM_CONV);
    cudaFuncSetAttribute((conv_mma<C1P, CC, 1>),  cudaFuncAttributeMaxDynamicSharedMemorySize, SMEM_CONV);

    // 1. weight prep
    prep_weights<<<(NPREP + 255) / 256, 256>>>(qkv_w, proj_w, fc1_w, fc2_w, cab_w1, cab_w2,
                                               p_wqh, p_wph, p_wf1h, p_wf2h, p_w1th, p_w2th);
    // 2. LN1
    ln_kernel<<<NTOK / 8, 256>>>(x, ln1_g, ln1_b, p_xnh, p_xnl, NTOK);
    // 3-4. conv branch
    conv_mma<KP, C1D, 0><<<dim3(1, 2048), 256, SMEM_CONV>>>(
        p_xnh, p_w1th, cab_b1, nullptr, p_c1h);
    conv_mma<C1P, CC, 1><<<dim3(3, 2048), 256, SMEM_CONV>>>(
        p_c1h, p_w2th, cab_b2, p_y, nullptr);
    // 5. pooling
    pool_partial_kernel<<<1024, 256>>>(p_y, p_poolp);
    // 6. QKV GEMM (profiled launch)
    mma_gemm<0><<<dim3(9, 2048), 256, SMEM_MMA>>>(p_xnh, p_xnl, p_wqh, qkv_b,
                                                  nullptr, nullptr, nullptr,
                                                  p_qkv, nullptr, nullptr, 540, KP, 0);
    // 7. channel attention
    ca_kernel<<<BATCH, 192>>>(p_poolp, ca_w1, ca_b1, ca_w2, ca_b2, p_a);
    // 8. window attention
    attn_kernel<<<NWIN, 256, smem_attn>>>(p_qkv, bias_table, rpi, p_atth, p_attl);
    // 9. proj + residual + conv add
    mma_gemm<2><<<dim3(3, 2048), 256, SMEM_MMA>>>(p_atth, p_attl, p_wph, proj_b,
                                                  x, p_y, p_a,
                                                  p_xmid, nullptr, nullptr, CC, KP, 0);
    // 10-12. MLP
    ln_kernel<<<NTOK / 8, 256>>>(p_xmid, ln2_g, ln2_b, p_xnh, p_xnl, NTOK);
    mma_gemm<1><<<dim3(12, 2048), 256, SMEM_MMA>>>(p_xnh, p_xnl, p_wf1h, fc1_b,
                                                   nullptr, nullptr, nullptr,
                                                   nullptr, p_hh, p_hl, FF, KP, FFP);
    mma_gemm<3><<<dim3(3, 2048), 256, SMEM_MMA>>>(p_hh, p_hl, p_wf2h, fc2_b,
                                                  p_xmid, nullptr, nullptr,
                                                  out, nullptr, nullptr, CC, FFP, 0);
}

// round 17
// speedup vs baseline: 2.1637x; 1.2724x over previous
#include <cuda_runtime.h>
#include <cuda_fp16.h>
#include <math.h>
#include <stdint.h>

// ---------------- Problem constants ----------------
#define BATCH   4
#define HW      65536
#define CC      180
#define KP      192            // padded K for C=180
#define C1D     60
#define C1P     64             // padded K for C=60
#define CAD     6
#define FF      720
#define FFP     768            // padded K for C=720
#define HEADS   6
#define HD      30
#define NTOK    262144
#define NWIN    4096

// ---------------- Scratch (zero-initialized; pad regions never written) ----------------
__device__ float g_qkv [(size_t)NTOK * 540];
__device__ float g_y   [NTOK * CC];
__device__ float g_xmid[NTOK * CC];
__device__ float g_poolp[1024 * CC];
__device__ float g_a   [BATCH * CC];

__device__ __half g_xnh[(size_t)NTOK * KP];
__device__ __half g_c1h[(size_t)NTOK * C1P];
__device__ __half g_atth[(size_t)NTOK * KP];
__device__ __half g_hh[(size_t)NTOK * FFP];
__device__ __half g_wqh[540 * KP];
__device__ __half g_wph[CC * KP];
__device__ __half g_wf1h[FF * KP];
__device__ __half g_wf2h[CC * FFP];
__device__ __half g_w1th[9 * C1D * KP];    // [tap][oc][ic]
__device__ __half g_w2th[9 * CC * C1P];    // [tap][oc][ic]

__device__ __forceinline__ float gelu_f(float x) {
    return 0.5f * x * (1.0f + erff(x * 0.70710678118654752f));
}
__device__ __forceinline__ uint32_t smem_u32(const void* p) {
    uint32_t a;
    asm("{ .reg .u64 t; cvta.to.shared.u64 t, %1; cvt.u32.u64 %0, t; }" : "=r"(a) : "l"(p));
    return a;
}
__device__ __forceinline__ void ldsm_x4(uint32_t* r, uint32_t addr) {
    asm volatile("ldmatrix.sync.aligned.m8n8.x4.shared.b16 {%0,%1,%2,%3}, [%4];"
        : "=r"(r[0]), "=r"(r[1]), "=r"(r[2]), "=r"(r[3]) : "r"(addr));
}
__device__ __forceinline__ void mma16816(float* c, const uint32_t* a, const uint32_t* b) {
    asm volatile("mma.sync.aligned.m16n8k16.row.col.f32.f16.f16.f32 "
        "{%0,%1,%2,%3}, {%4,%5,%6,%7}, {%8,%9}, {%0,%1,%2,%3};"
        : "+f"(c[0]), "+f"(c[1]), "+f"(c[2]), "+f"(c[3])
        : "r"(a[0]), "r"(a[1]), "r"(a[2]), "r"(a[3]), "r"(b[0]), "r"(b[1]));
}
__device__ __forceinline__ void cp16(uint32_t saddr, const void* g, uint32_t bytes) {
    asm volatile("cp.async.cg.shared.global [%0], [%1], 16, %2;"
        :: "r"(saddr), "l"(g), "r"(bytes));
}
__device__ __forceinline__ void cp_commit() { asm volatile("cp.async.commit_group;"); }
template<int N> __device__ __forceinline__ void cp_wait() {
    asm volatile("cp.async.wait_group %0;" :: "n"(N));
}

// ---------------- fused weight prep (fp32 -> fp16, padded strides) ----------------
#define NWQ  (540*CC)
#define NWP  (CC*CC)
#define NWF1 (FF*CC)
#define NWF2 (CC*FF)
#define NW1  (9*C1D*CC)
#define NW2  (9*CC*C1D)
__global__ void prep_weights(const float* __restrict__ wq, const float* __restrict__ wp,
                             const float* __restrict__ wf1, const float* __restrict__ wf2,
                             const float* __restrict__ cw1, const float* __restrict__ cw2,
                             __half* __restrict__ dq, __half* __restrict__ dp,
                             __half* __restrict__ df1, __half* __restrict__ df2,
                             __half* __restrict__ d1t, __half* __restrict__ d2t) {
    int i = blockIdx.x * 256 + threadIdx.x;
    if (i < NWQ) { dq[(i / CC) * KP + i % CC] = __float2half_rn(wq[i]); return; }
    i -= NWQ;
    if (i < NWP) { dp[(i / CC) * KP + i % CC] = __float2half_rn(wp[i]); return; }
    i -= NWP;
    if (i < NWF1) { df1[(i / CC) * KP + i % CC] = __float2half_rn(wf1[i]); return; }
    i -= NWF1;
    if (i < NWF2) { df2[(i / FF) * FFP + i % FF] = __float2half_rn(wf2[i]); return; }
    i -= NWF2;
    if (i < NW1) {
        int tap = i % 9, ic = (i / 9) % CC, oc = i / (9 * CC);
        d1t[(size_t)tap * C1D * KP + (size_t)oc * KP + ic] = __float2half_rn(cw1[i]);
        return;
    }
    i -= NW1;
    if (i < NW2) {
        int tap = i % 9, ic = (i / 9) % C1D, oc = i / (9 * C1D);
        d2t[(size_t)tap * CC * C1P + (size_t)oc * C1P + ic] = __float2half_rn(cw2[i]);
    }
}
#define NPREP (NWQ + NWP + NWF1 + NWF2 + NW1 + NW2)

// ---------------- LayerNorm: fp16 (padded stride KP, zeros in pad) ----------------
__global__ void ln_kernel(const float* __restrict__ in, const float* __restrict__ g,
                          const float* __restrict__ bt,
                          __half* __restrict__ oh, int ntok) {
    int gwarp = (blockIdx.x * blockDim.x + threadIdx.x) >> 5;
    int lane  = threadIdx.x & 31;
    if (gwarp >= ntok) return;
    const float* p = in + (size_t)gwarp * CC;
    float v[6]; float s = 0.f, s2 = 0.f;
#pragma unroll
    for (int k = 0; k < 6; k++) {
        int c = lane + 32 * k;
        float xv = (c < CC) ? p[c] : 0.f;
        v[k] = xv; s += xv; s2 += xv * xv;
    }
#pragma unroll
    for (int o = 16; o > 0; o >>= 1) {
        s  += __shfl_xor_sync(0xffffffffu, s,  o);
        s2 += __shfl_xor_sync(0xffffffffu, s2, o);
    }
    float mean = s * (1.f / CC);
    float var  = s2 * (1.f / CC) - mean * mean;
    float inv  = rsqrtf(var + 1e-5f);
    size_t base = (size_t)gwarp * KP;
#pragma unroll
    for (int k = 0; k < 6; k++) {
        int c = lane + 32 * k;    // 0..191 — pad written with zeros
        float y = (c < CC) ? ((v[k] - mean) * inv * g[c] + bt[c]) : 0.f;
        oh[base + c] = __float2half_rn(y);
    }
}

// ---------------- tile geometry (single-precision-pass buffers) ----------------
#define LDT 72
#define E_B  9216                  // B tile offset (halves)
#define BUF_E 13824                // A [128x72] + B [64x72]
#define SMEM_MMA (2 * BUF_E * 2)   // 55296 B

// ---------------- fp16 mma.sync GEMM, single-pass, cp16 staging ----------------
// MODE 0: fp32 +bias | 1: gelu(+bias)->fp16 (stride ldo) | 2: proj epi | 3: fc2 epi
template<int MODE>
__global__ __launch_bounds__(256)
void mma_gemm(const __half* __restrict__ Ah, const __half* __restrict__ Bh,
              const float* __restrict__ bias,
              const float* __restrict__ aux1, const float* __restrict__ aux2,
              const float* __restrict__ ga,
              float* __restrict__ outf, __half* __restrict__ outh,
              int N, int K, int ldo)
{
    extern __shared__ __half sm[];
    const uint32_t sbase = smem_u32(sm);
    const int tid  = threadIdx.x;
    const int warp = tid >> 5, lane = tid & 31;
    const int wm = warp >> 1, wn = warp & 1;
    const size_t m0 = (size_t)blockIdx.y * 128;
    const int n0 = blockIdx.x * 64;

    float acc[2][4][4];
#pragma unroll
    for (int i = 0; i < 2; i++)
#pragma unroll
        for (int j = 0; j < 4; j++)
#pragma unroll
            for (int c = 0; c < 4; c++) acc[i][j][c] = 0.f;

    const int aRow = (lane & 15), aColOff = (lane >> 4) << 3;
    const int bRow = ((lane >> 4) << 3) + (lane & 7), bColOff = ((lane >> 3) & 1) << 3;
    const int nch = K >> 6;

#define G_STAGE(buf, kc) do { \
    const int kbase = (kc) * 64; \
    const uint32_t bb = sbase + (uint32_t)(buf) * (BUF_E * 2); \
    for (int i = tid; i < 1024; i += 256) { \
        int row = i >> 3, c = i & 7; \
        size_t off = (m0 + row) * (size_t)K + kbase + c * 8; \
        cp16(bb + (uint32_t)(row * LDT + c * 8) * 2, Ah + off, 16); \
    } \
    for (int i = tid; i < 512; i += 256) { \
        int row = i >> 3, c = i & 7; \
        int n_ = n0 + row; \
        uint32_t vb = (n_ < N) ? 16u : 0u; \
        size_t off = (n_ < N) ? ((size_t)n_ * K + kbase + c * 8) : 0; \
        cp16(bb + (uint32_t)(E_B + row * LDT + c * 8) * 2, Bh + off, vb); \
    } \
} while (0)

    G_STAGE(0, 0);
    cp_commit();
    for (int kc = 0; kc < nch; kc++) {
        const int cur = kc & 1;
        if (kc + 1 < nch) { G_STAGE(cur ^ 1, kc + 1); cp_commit(); cp_wait<1>(); }
        else cp_wait<0>();
        __syncthreads();

        const uint32_t bb = sbase + (uint32_t)cur * (BUF_E * 2);
        const uint32_t aBase = bb + (uint32_t)((wm * 32 + aRow) * LDT + aColOff) * 2;
        const uint32_t bBase = bb + (uint32_t)(E_B + (wn * 32 + bRow) * LDT + bColOff) * 2;
#pragma unroll
        for (int ks = 0; ks < 4; ks++) {
            const uint32_t kb2 = (uint32_t)(ks * 16) * 2;
            uint32_t aH[2][4], bH[4][2];
#pragma unroll
            for (int mi = 0; mi < 2; mi++)
                ldsm_x4(aH[mi], aBase + kb2 + (uint32_t)(mi * 16 * LDT) * 2);
#pragma unroll
            for (int nf = 0; nf < 2; nf++) {
                uint32_t t[4];
                ldsm_x4(t, bBase + kb2 + (uint32_t)(nf * 16 * LDT) * 2);
                bH[nf*2][0] = t[0]; bH[nf*2][1] = t[1];
                bH[nf*2+1][0] = t[2]; bH[nf*2+1][1] = t[3];
            }
#pragma unroll
            for (int mi = 0; mi < 2; mi++)
#pragma unroll
                for (int ni = 0; ni < 4; ni++)
                    mma16816(acc[mi][ni], aH[mi], bH[ni]);
        }
        __syncthreads();
    }
#undef G_STAGE

#pragma unroll
    for (int mi = 0; mi < 2; mi++)
#pragma unroll
        for (int hh = 0; hh < 2; hh++) {
            size_t row = m0 + wm * 32 + mi * 16 + (lane >> 2) + hh * 8;
            int bb = (int)(row >> 16);
#pragma unroll
            for (int ni = 0; ni < 4; ni++) {
                int n_ = n0 + wn * 32 + ni * 8 + (lane & 3) * 2;
                if (n_ >= N) continue;
                float v0 = acc[mi][ni][hh * 2 + 0] + bias[n_];
                float v1 = acc[mi][ni][hh * 2 + 1] + bias[n_ + 1];
                if (MODE == 0) {
                    size_t o = row * (size_t)N + n_;
                    *(float2*)(outf + o) = make_float2(v0, v1);
                } else if (MODE == 1) {
                    size_t o = row * (size_t)ldo + n_;
                    *(__half2*)(outh + o) = __halves2half2(
                        __float2half_rn(gelu_f(v0)), __float2half_rn(gelu_f(v1)));
                } else if (MODE == 2) {
                    size_t o = row * (size_t)N + n_;
                    float2 xv = *(const float2*)(aux1 + o);
                    float2 yv = *(const float2*)(aux2 + o);
                    *(float2*)(outf + o) = make_float2(
                        xv.x + v0 + yv.x * ga[bb * CC + n_],
                        xv.y + v1 + yv.y * ga[bb * CC + n_ + 1]);
                } else {
                    size_t o = row * (size_t)N + n_;
                    float2 xm = *(const float2*)(aux1 + o);
                    *(float2*)(outf + o) = make_float2(xm.x + v0, xm.y + v1);
                }
            }
        }
}

// ---------------- implicit-GEMM 3x3 conv, single-pass fp16, cp16 staging ----------------
// KSP: padded K stride; CMODE 0: gelu(+bias)->fp16 | 1: fp32 +bias
template<int KSP, int OSTR, int CMODE>
__global__ __launch_bounds__(256)
void conv_mma(const __half* __restrict__ Ah, const __half* __restrict__ Wh,
              const float* __restrict__ bias,
              float* __restrict__ outf, __half* __restrict__ outh)
{
    extern __shared__ __half sm[];
    const uint32_t sbase = smem_u32(sm);
    const int tid  = threadIdx.x;
    const int warp = tid >> 5, lane = tid & 31;
    const int wm = warp >> 1, wn = warp & 1;
    const size_t m0 = (size_t)blockIdx.y * 128;
    const int oc0 = blockIdx.x * 60;
    const int NCH = KSP >> 6;

    float acc[2][4][4];
#pragma unroll
    for (int i = 0; i < 2; i++)
#pragma unroll
        for (int j = 0; j < 4; j++)
#pragma unroll
            for (int c = 0; c < 4; c++) acc[i][j][c] = 0.f;

    const int aRow = (lane & 15), aColOff = (lane >> 4) << 3;
    const int bRow = ((lane >> 4) << 3) + (lane & 7), bColOff = ((lane >> 3) & 1) << 3;
    const int NIT = 9 * NCH;

#define C_STAGE(buf, it) do { \
    const int tap = (it) / NCH; \
    const int kbase = ((it) % NCH) * 64; \
    const int dr = tap / 3 - 1, dc = tap % 3 - 1; \
    const int toff = dr * 256 + dc; \
    const uint32_t bb = sbase + (uint32_t)(buf) * (BUF_E * 2); \
    for (int i = tid; i < 1024; i += 256) { \
        int row = i >> 3, c = i & 7; \
        int t = (int)(m0 + row); \
        int hh2 = (t >> 8) & 255, ww2 = t & 255; \
        bool ok = ((unsigned)(hh2 + dr) < 256u) && ((unsigned)(ww2 + dc) < 256u); \
        uint32_t vb = ok ? 16u : 0u; \
        size_t off = ok ? ((size_t)(t + toff) * KSP + kbase + c * 8) : 0; \
        cp16(bb + (uint32_t)(row * LDT + c * 8) * 2, Ah + off, vb); \
    } \
    for (int i = tid; i < 512; i += 256) { \
        int n = i >> 3, c = i & 7; \
        uint32_t vb = (n < 60) ? 16u : 0u; \
        size_t off = (n < 60) ? ((size_t)tap * OSTR * KSP + (size_t)(oc0 + n) * KSP + kbase + c * 8) : 0; \
        cp16(bb + (uint32_t)(E_B + n * LDT + c * 8) * 2, Wh + off, vb); \
    } \
} while (0)

    C_STAGE(0, 0);
    cp_commit();
    for (int it = 0; it < NIT; it++) {
        const int cur = it & 1;
        if (it + 1 < NIT) { C_STAGE(cur ^ 1, it + 1); cp_commit(); cp_wait<1>(); }
        else cp_wait<0>();
        __syncthreads();

        const uint32_t bb = sbase + (uint32_t)cur * (BUF_E * 2);
        const uint32_t aBase = bb + (uint32_t)((wm * 32 + aRow) * LDT + aColOff) * 2;
        const uint32_t bBase = bb + (uint32_t)(E_B + (wn * 32 + bRow) * LDT + bColOff) * 2;
#pragma unroll
        for (int ks = 0; ks < 4; ks++) {
            const uint32_t kb2 = (uint32_t)(ks * 16) * 2;
            uint32_t aH[2][4], bH[4][2];
#pragma unroll
            for (int mi = 0; mi < 2; mi++)
                ldsm_x4(aH[mi], aBase + kb2 + (uint32_t)(mi * 16 * LDT) * 2);
#pragma unroll
            for (int nf = 0; nf < 2; nf++) {
                uint32_t t4[4];
                ldsm_x4(t4, bBase + kb2 + (uint32_t)(nf * 16 * LDT) * 2);
                bH[nf*2][0] = t4[0]; bH[nf*2][1] = t4[1];
                bH[nf*2+1][0] = t4[2]; bH[nf*2+1][1] = t4[3];
            }
#pragma unroll
            for (int mi = 0; mi < 2; mi++)
#pragma unroll
                for (int ni = 0; ni < 4; ni++)
                    mma16816(acc[mi][ni], aH[mi], bH[ni]);
        }
        __syncthreads();
    }
#undef C_STAGE

#pragma unroll
    for (int mi = 0; mi < 2; mi++)
#pragma unroll
        for (int hh = 0; hh < 2; hh++) {
            size_t row = m0 + wm * 32 + mi * 16 + (lane >> 2) + hh * 8;
#pragma unroll
            for (int ni = 0; ni < 4; ni++) {
                int n_ = wn * 32 + ni * 8 + (lane & 3) * 2;
                if (n_ >= 60) continue;
                int oc = oc0 + n_;
                float v0 = acc[mi][ni][hh * 2 + 0] + bias[oc];
                float v1 = acc[mi][ni][hh * 2 + 1] + bias[oc + 1];
                if (CMODE == 0) {
                    size_t o = row * (size_t)C1P + oc;
                    *(__half2*)(outh + o) = __halves2half2(
                        __float2half_rn(gelu_f(v0)), __float2half_rn(gelu_f(v1)));
                } else {
                    size_t o = row * (size_t)CC + oc;
                    *(float2*)(outf + o) = make_float2(v0, v1);
                }
            }
        }
}

// ---------------- channel pooling (stage 1) ----------------
__global__ __launch_bounds__(256)
void pool_partial_kernel(const float* __restrict__ y, float* __restrict__ pp) {
    __shared__ float s[64 * CC];
    int tid = threadIdx.x;
    int blk = blockIdx.x;
    size_t base = (size_t)blk * 256 * CC;
    float acc = 0.f;
    for (int it = 0; it < 4; it++) {
        __syncthreads();
        const float4* src = (const float4*)(y + base + (size_t)it * 64 * CC);
        float4* d4 = (float4*)s;
        for (int i = tid; i < 64 * CC / 4; i += 256) d4[i] = src[i];
        __syncthreads();
        if (tid < CC) {
#pragma unroll
            for (int t = 0; t < 64; t++) acc += s[t * CC + tid];
        }
    }
    if (tid < CC) pp[blk * CC + tid] = acc;
}

// ---------------- channel attention ----------------
__global__ void ca_kernel(const float* __restrict__ poolp,
                          const float* __restrict__ w1, const float* __restrict__ b1,
                          const float* __restrict__ w2, const float* __restrict__ b2,
                          float* __restrict__ ga) {
    int b = blockIdx.x;
    int t = threadIdx.x;
    __shared__ float mean[CC];
    __shared__ float sq[CAD];
    if (t < CC) {
        float a = 0.f;
        for (int k = 0; k < 256; k++) a += poolp[(size_t)(b * 256 + k) * CC + t];
        mean[t] = a * (1.f / 65536.f);
    }
    __syncthreads();
    if (t < CAD) {
        float a = b1[t];
        for (int c = 0; c < CC; c++) a += mean[c] * w1[t * CC + c];
        sq[t] = fmaxf(a, 0.f);
    }
    __syncthreads();
    if (t < CC) {
        float a = b2[t];
#pragma unroll
        for (int j = 0; j < CAD; j++) a += sq[j] * w2[t * CAD + j];
        ga[b * CC + t] = 0.01f / (1.f + expf(-a));
    }
}

// ---------------- window attention (fp16 out, padded stride) ----------------
__global__ __launch_bounds__(256)
void attn_kernel(const float* __restrict__ qkv, const float* __restrict__ bias_table,
                 const int* __restrict__ rpi, __half* __restrict__ atth) {
    extern __shared__ float smf[];
    float* sQ = smf;
    float* sK = sQ + 64 * 33;
    float* sV = sK + 64 * 33;
    float* sA = sV + 64 * 33;
    int*   sR = (int*)(sA + 64 * 66);

    const int tid = threadIdx.x;
    const int b   = blockIdx.x >> 10;
    const int win = blockIdx.x & 1023;
    const int wr  = win >> 5, wc = win & 31;
    const int row0 = b * HW + (wr * 8) * 256 + wc * 8;

    for (int idx = tid; idx < 4096; idx += 256) sR[idx] = rpi[idx];

    const float scale = 0.18257418583505536f;
    for (int h = 0; h < HEADS; h++) {
        __syncthreads();
        for (int idx = tid; idx < 1920; idx += 256) {
            int i = idx / 30, d = idx % 30;
            int gt = row0 + (i >> 3) * 256 + (i & 7);
            const float* p = qkv + (size_t)gt * 540 + h * HD + d;
            sQ[i * 33 + d] = p[0] * scale;
            sK[i * 33 + d] = p[180];
            sV[i * 33 + d] = p[360];
        }
        __syncthreads();
        for (int idx = tid; idx < 2048; idx += 256) {
            int j = idx & 63, ip = idx >> 6;
            int i0 = ip * 2, i1 = i0 + 1;
            float s0 = bias_table[sR[i0 * 64 + j] * HEADS + h];
            float s1 = bias_table[sR[i1 * 64 + j] * HEADS + h];
            const float* q0 = sQ + i0 * 33;
            const float* q1 = sQ + i1 * 33;
            const float* kp = sK + j * 33;
#pragma unroll
            for (int d = 0; d < HD; d++) {
                float kv = kp[d];
                s0 += q0[d] * kv; s1 += q1[d] * kv;
            }
            sA[i0 * 66 + j] = s0; sA[i1 * 66 + j] = s1;
        }
        __syncthreads();
        {
            int w = tid >> 5, lane = tid & 31;
            for (int rrow = w; rrow < 64; rrow += 8) {
                float* row = sA + rrow * 66;
                float v0 = row[lane], v1 = row[lane + 32];
                float m = fmaxf(v0, v1);
#pragma unroll
                for (int o = 16; o > 0; o >>= 1) m = fmaxf(m, __shfl_xor_sync(0xffffffffu, m, o));
                float e0 = expf(v0 - m), e1 = expf(v1 - m);
                float s = e0 + e1;
#pragma unroll
                for (int o = 16; o > 0; o >>= 1) s += __shfl_xor_sync(0xffffffffu, s, o);
                float inv = 1.f / s;
                row[lane] = e0 * inv; row[lane + 32] = e1 * inv;
            }
        }
        __syncthreads();
        for (int idx = tid; idx < 960; idx += 256) {
            int d = idx % 30, ip = idx / 30;
            int i0 = ip * 2, i1 = i0 + 1;
            const float* a0 = sA + i0 * 66;
            const float* a1 = sA + i1 * 66;
            float o0 = 0.f, o1 = 0.f;
#pragma unroll 8
            for (int j = 0; j < 64; j++) {
                float vv = sV[j * 33 + d];
                o0 += a0[j] * vv; o1 += a1[j] * vv;
            }
            int gt0 = row0 + (i0 >> 3) * 256 + (i0 & 7);
            int gt1 = row0 + (i1 >> 3) * 256 + (i1 & 7);
            atth[(size_t)gt0 * KP + h * HD + d] = __float2half_rn(o0);
            atth[(size_t)gt1 * KP + h * HD + d] = __float2half_rn(o1);
        }
    }
}

// ---------------- host launch ----------------
extern "C" void kernel_launch(void* const* d_in, const int* in_sizes, int n_in,
                              void* d_out, int out_size) {
    const float* x          = (const float*)d_in[0];
    const float* ln1_g      = (const float*)d_in[1];
    const float* ln1_b      = (const float*)d_in[2];
    const float* qkv_w      = (const float*)d_in[3];
    const float* qkv_b      = (const float*)d_in[4];
    const float* bias_table = (const float*)d_in[5];
    const float* proj_w     = (const float*)d_in[6];
    const float* proj_b     = (const float*)d_in[7];
    const float* cab_w1     = (const float*)d_in[8];
    const float* cab_b1     = (const float*)d_in[9];
    const float* cab_w2     = (const float*)d_in[10];
    const float* cab_b2     = (const float*)d_in[11];
    const float* ca_w1      = (const float*)d_in[12];
    const float* ca_b1      = (const float*)d_in[13];
    const float* ca_w2      = (const float*)d_in[14];
    const float* ca_b2      = (const float*)d_in[15];
    const float* ln2_g      = (const float*)d_in[16];
    const float* ln2_b      = (const float*)d_in[17];
    const float* fc1_w      = (const float*)d_in[18];
    const float* fc1_b      = (const float*)d_in[19];
    const float* fc2_w      = (const float*)d_in[20];
    const float* fc2_b      = (const float*)d_in[21];
    const int*   rpi        = (const int*)d_in[22];
    float* out = (float*)d_out;

    float *p_qkv, *p_y, *p_xmid, *p_poolp, *p_a;
    __half *p_xnh, *p_c1h, *p_atth, *p_hh;
    __half *p_wqh, *p_wph, *p_wf1h, *p_wf2h, *p_w1th, *p_w2th;
    cudaGetSymbolAddress((void**)&p_qkv,   g_qkv);
    cudaGetSymbolAddress((void**)&p_y,     g_y);
    cudaGetSymbolAddress((void**)&p_xmid,  g_xmid);
    cudaGetSymbolAddress((void**)&p_poolp, g_poolp);
    cudaGetSymbolAddress((void**)&p_a,     g_a);
    cudaGetSymbolAddress((void**)&p_xnh,   g_xnh);
    cudaGetSymbolAddress((void**)&p_c1h,   g_c1h);
    cudaGetSymbolAddress((void**)&p_atth,  g_atth);
    cudaGetSymbolAddress((void**)&p_hh,    g_hh);
    cudaGetSymbolAddress((void**)&p_wqh,   g_wqh);
    cudaGetSymbolAddress((void**)&p_wph,   g_wph);
    cudaGetSymbolAddress((void**)&p_wf1h,  g_wf1h);
    cudaGetSymbolAddress((void**)&p_wf2h,  g_wf2h);
    cudaGetSymbolAddress((void**)&p_w1th,  g_w1th);
    cudaGetSymbolAddress((void**)&p_w2th,  g_w2th);

    const int smem_attn = (3 * 64 * 33 + 64 * 66) * 4 + 4096 * 4;

    cudaFuncSetAttribute(attn_kernel,  cudaFuncAttributeMaxDynamicSharedMemorySize, smem_attn);
    cudaFuncSetAttribute(mma_gemm<0>, cudaFuncAttributeMaxDynamicSharedMemorySize, SMEM_MMA);
    cudaFuncSetAttribute(mma_gemm<1>, cudaFuncAttributeMaxDynamicSharedMemorySize, SMEM_MMA);
    cudaFuncSetAttribute(mma_gemm<2>, cudaFuncAttributeMaxDynamicSharedMemorySize, SMEM_MMA);
    cudaFuncSetAttribute(mma_gemm<3>, cudaFuncAttributeMaxDynamicSharedMemorySize, SMEM_MMA);
    cudaFuncSetAttribute((conv_mma<KP, C1D, 0>),  cudaFuncAttributeMaxDynamicSharedMemorySize, SMEM_MMA);
    cudaFuncSetAttribute((conv_mma<C1P, CC, 1>),  cudaFuncAttributeMaxDynamicSharedMemorySize, SMEM_MMA);

    // 1. weight prep
    prep_weights<<<(NPREP + 255) / 256, 256>>>(qkv_w, proj_w, fc1_w, fc2_w, cab_w1, cab_w2,
                                               p_wqh, p_wph, p_wf1h, p_wf2h, p_w1th, p_w2th);
    // 2. LN1
    ln_kernel<<<NTOK / 8, 256>>>(x, ln1_g, ln1_b, p_xnh, NTOK);
    // 3-4. conv branch
    conv_mma<KP, C1D, 0><<<dim3(1, 2048), 256, SMEM_MMA>>>(
        p_xnh, p_w1th, cab_b1, nullptr, p_c1h);
    conv_mma<C1P, CC, 1><<<dim3(3, 2048), 256, SMEM_MMA>>>(
        p_c1h, p_w2th, cab_b2, p_y, nullptr);
    // 5. pooling
    pool_partial_kernel<<<1024, 256>>>(p_y, p_poolp);
    // 6. QKV GEMM (profiled launch)
    mma_gemm<0><<<dim3(9, 2048), 256, SMEM_MMA>>>(p_xnh, p_wqh, qkv_b,
                                                  nullptr, nullptr, nullptr,
                                                  p_qkv, nullptr, 540, KP, 0);
    // 7. channel attention
    ca_kernel<<<BATCH, 192>>>(p_poolp, ca_w1, ca_b1, ca_w2, ca_b2, p_a);
    // 8. window attention
    attn_kernel<<<NWIN, 256, smem_attn>>>(p_qkv, bias_table, rpi, p_atth);
    // 9. proj + residual + conv add
    mma_gemm<2><<<dim3(3, 2048), 256, SMEM_MMA>>>(p_atth, p_wph, proj_b,
                                                  x, p_y, p_a,
                                                  p_xmid, nullptr, CC, KP, 0);
    // 10-12. MLP
    ln_kernel<<<NTOK / 8, 256>>>(p_xmid, ln2_g, ln2_b, p_xnh, NTOK);
    mma_gemm<1><<<dim3(12, 2048), 256, SMEM_MMA>>>(p_xnh, p_wf1h, fc1_b,
                                                   nullptr, nullptr, nullptr,
                                                   nullptr, p_hh, FF, KP, FFP);
    mma_gemm<3><<<dim3(3, 2048), 256, SMEM_MMA>>>(p_hh, p_wf2h, fc2_b,
                                                  p_xmid, nullptr, nullptr,
                                                  out, nullptr, CC, FFP, 0);
}